// round 1
// baseline (speedup 1.0000x reference)
#include <cuda_runtime.h>
#include <math.h>

#define S_LEN  2048
#define HIDDEN 2048
#define NH     32
#define NKV    8
#define HD     64

// Scratch (device globals — no allocation allowed in kernel_launch)
__device__ float g_q[S_LEN * NH * HD];      // [s, h, d]
__device__ float g_k[S_LEN * NKV * HD];     // [s, kvh, d]
__device__ float g_v[S_LEN * NKV * HD];     // [s, kvh, d]
__device__ float g_attn[S_LEN * NH * HD];   // [s, h*64+d]

// ---------------------------------------------------------------------------
// SGEMM: C[M,N] = A[M,K] @ B[K,N], row-major fp32.
// 128x128 block, BK=8, 256 threads, 8x8 microtile per thread.
// ---------------------------------------------------------------------------
#define BM 128
#define BN 128
#define BK 8

__global__ __launch_bounds__(256) void sgemm_kernel(
    const float* __restrict__ A, const float* __restrict__ B,
    float* __restrict__ C, int M, int N, int K)
{
    __shared__ float As[BK][BM];
    __shared__ float Bs[BK][BN];

    const int tid = threadIdx.x;
    const int bm  = blockIdx.y * BM;
    const int bn  = blockIdx.x * BN;
    const int tx  = tid & 15;       // 0..15 -> 8 cols each
    const int ty  = tid >> 4;       // 0..15 -> 8 rows each

    // A tile load: 128 rows x 8 cols, one float4 per thread
    const int a_row = tid >> 1;           // 0..127
    const int a_col = (tid & 1) * 4;      // 0 or 4
    // B tile load: 8 rows x 128 cols, one float4 per thread
    const int b_row = tid >> 5;           // 0..7
    const int b_col = (tid & 31) * 4;     // 0..124

    const float* Aptr = A + (size_t)(bm + a_row) * K + a_col;
    const float* Bptr = B + (size_t)b_row * N + bn + b_col;

    float acc[8][8];
    #pragma unroll
    for (int i = 0; i < 8; ++i)
        #pragma unroll
        for (int j = 0; j < 8; ++j)
            acc[i][j] = 0.0f;

    for (int k0 = 0; k0 < K; k0 += BK) {
        float4 av = *(const float4*)(Aptr + k0);
        float4 bv = *(const float4*)(Bptr + (size_t)k0 * N);
        __syncthreads();   // protect previous iteration's smem reads
        As[a_col + 0][a_row] = av.x;
        As[a_col + 1][a_row] = av.y;
        As[a_col + 2][a_row] = av.z;
        As[a_col + 3][a_row] = av.w;
        *(float4*)&Bs[b_row][b_col] = bv;
        __syncthreads();

        #pragma unroll
        for (int k = 0; k < BK; ++k) {
            float af[8], bf[8];
            *(float4*)&af[0] = *(const float4*)&As[k][ty * 8];
            *(float4*)&af[4] = *(const float4*)&As[k][ty * 8 + 4];
            *(float4*)&bf[0] = *(const float4*)&Bs[k][tx * 8];
            *(float4*)&bf[4] = *(const float4*)&Bs[k][tx * 8 + 4];
            #pragma unroll
            for (int i = 0; i < 8; ++i)
                #pragma unroll
                for (int j = 0; j < 8; ++j)
                    acc[i][j] += af[i] * bf[j];
        }
    }

    #pragma unroll
    for (int i = 0; i < 8; ++i) {
        float* crow = C + (size_t)(bm + ty * 8 + i) * N + bn + tx * 8;
        *(float4*)crow       = make_float4(acc[i][0], acc[i][1], acc[i][2], acc[i][3]);
        *(float4*)(crow + 4) = make_float4(acc[i][4], acc[i][5], acc[i][6], acc[i][7]);
    }
}

// ---------------------------------------------------------------------------
// RoPE (interleaved pairs), in place over x: [S, nheads, 64]
// ---------------------------------------------------------------------------
__global__ void rope_kernel(float* __restrict__ x, int nheads)
{
    int idx = blockIdx.x * blockDim.x + threadIdx.x;
    int total = S_LEN * nheads * (HD / 2);
    if (idx >= total) return;
    int i    = idx & (HD / 2 - 1);   // 0..31 pair index
    int rest = idx >> 5;
    int h    = rest % nheads;
    int s    = rest / nheads;

    // inv_freq = 500000^(-(2i)/64), computed in double for accuracy
    double e = -((double)(2 * i) / (double)HD) * log(500000.0);
    float freq = (float)exp(e);
    float ang = (float)s * freq;
    float sn, cs;
    sincosf(ang, &sn, &cs);   // accurate range reduction (ang up to ~2048 rad)

    float* p = x + ((size_t)s * nheads + h) * HD + 2 * i;
    float x1 = p[0], x2 = p[1];
    p[0] = x1 * cs - x2 * sn;
    p[1] = x1 * sn + x2 * cs;
}

// ---------------------------------------------------------------------------
// Causal GQA flash attention.
// Grid: (S/128 q-tiles, 32 heads). 128 threads, one query row per thread.
// K/V tiles of 64 keys staged in smem; online softmax with 16-key chunks.
// ---------------------------------------------------------------------------
#define QTILE 128
#define KTILE 64

__global__ __launch_bounds__(128) void attn_kernel(
    const float* __restrict__ Q, const float* __restrict__ K,
    const float* __restrict__ V, float* __restrict__ O)
{
    __shared__ float Ksh[KTILE][HD];
    __shared__ float Vsh[KTILE][HD];

    const int h   = blockIdx.y;
    const int kvh = h >> 2;                 // GROUPS = 4
    const int q0  = blockIdx.x * QTILE;
    const int tid = threadIdx.x;
    const int q   = q0 + tid;

    // Load scaled query row into registers
    float qreg[HD];
    const float* qptr = Q + ((size_t)q * NH + h) * HD;
    #pragma unroll
    for (int d = 0; d < HD; d += 4) {
        float4 t = *(const float4*)(qptr + d);
        qreg[d + 0] = t.x * 0.125f;
        qreg[d + 1] = t.y * 0.125f;
        qreg[d + 2] = t.z * 0.125f;
        qreg[d + 3] = t.w * 0.125f;
    }

    float m = -INFINITY, l = 0.0f;
    float4 accv[16];
    #pragma unroll
    for (int i = 0; i < 16; ++i) accv[i] = make_float4(0.f, 0.f, 0.f, 0.f);

    const int kend = q0 + QTILE;  // causal: keys beyond q-tile never needed
    for (int kt = 0; kt < kend; kt += KTILE) {
        __syncthreads();
        {
            int row = tid >> 1;
            int off = (tid & 1) * 32;
            const float4* ksrc = (const float4*)(K + ((size_t)(kt + row) * NKV + kvh) * HD + off);
            const float4* vsrc = (const float4*)(V + ((size_t)(kt + row) * NKV + kvh) * HD + off);
            float4* kdst = (float4*)&Ksh[row][off];
            float4* vdst = (float4*)&Vsh[row][off];
            #pragma unroll
            for (int i = 0; i < 8; ++i) { kdst[i] = ksrc[i]; vdst[i] = vsrc[i]; }
        }
        __syncthreads();

        for (int jc = 0; jc < KTILE; jc += 16) {
            float s[16];
            float mloc = -INFINITY;
            #pragma unroll
            for (int jj = 0; jj < 16; ++jj) {
                const float4* kr = (const float4*)Ksh[jc + jj];
                float sum = 0.0f;
                #pragma unroll
                for (int d4 = 0; d4 < 16; ++d4) {
                    float4 kv = kr[d4];
                    sum += qreg[4 * d4 + 0] * kv.x;
                    sum += qreg[4 * d4 + 1] * kv.y;
                    sum += qreg[4 * d4 + 2] * kv.z;
                    sum += qreg[4 * d4 + 3] * kv.w;
                }
                s[jj] = (kt + jc + jj <= q) ? sum : -INFINITY;
                mloc  = fmaxf(mloc, s[jj]);
            }
            float mnew = fmaxf(m, mloc);
            float corr = __expf(m - mnew);   // first chunk: exp(-inf)=0, safe
            l *= corr;
            #pragma unroll
            for (int i = 0; i < 16; ++i) {
                accv[i].x *= corr; accv[i].y *= corr;
                accv[i].z *= corr; accv[i].w *= corr;
            }
            #pragma unroll
            for (int jj = 0; jj < 16; ++jj) {
                float p = __expf(s[jj] - mnew);
                l += p;
                const float4* vr = (const float4*)Vsh[jc + jj];
                #pragma unroll
                for (int d4 = 0; d4 < 16; ++d4) {
                    float4 vv = vr[d4];
                    accv[d4].x += p * vv.x;
                    accv[d4].y += p * vv.y;
                    accv[d4].z += p * vv.z;
                    accv[d4].w += p * vv.w;
                }
            }
            m = mnew;
        }
    }

    float inv = 1.0f / l;
    float* optr = O + ((size_t)q * NH + h) * HD;
    #pragma unroll
    for (int d4 = 0; d4 < 16; ++d4) {
        float4 r;
        r.x = accv[d4].x * inv; r.y = accv[d4].y * inv;
        r.z = accv[d4].z * inv; r.w = accv[d4].w * inv;
        *(float4*)(optr + 4 * d4) = r;
    }
}

// ---------------------------------------------------------------------------
// Launch: QKV GEMMs -> RoPE(Q,K) -> attention -> output projection
// Inputs: 0=hidden_states, 1=attention_mask (ignored; causal known),
//         2=wq, 3=wk, 4=wv, 5=wo
// ---------------------------------------------------------------------------
extern "C" void kernel_launch(void* const* d_in, const int* in_sizes, int n_in,
                              void* d_out, int out_size)
{
    const float* x  = (const float*)d_in[0];
    const float* wq = (const float*)d_in[2];
    const float* wk = (const float*)d_in[3];
    const float* wv = (const float*)d_in[4];
    const float* wo = (const float*)d_in[5];
    float* out = (float*)d_out;

    float *q, *k, *v, *a;
    cudaGetSymbolAddress((void**)&q, g_q);
    cudaGetSymbolAddress((void**)&k, g_k);
    cudaGetSymbolAddress((void**)&v, g_v);
    cudaGetSymbolAddress((void**)&a, g_attn);

    sgemm_kernel<<<dim3((NH * HD) / BN, S_LEN / BM), 256>>>(x, wq, q, S_LEN, NH * HD, HIDDEN);
    sgemm_kernel<<<dim3((NKV * HD) / BN, S_LEN / BM), 256>>>(x, wk, k, S_LEN, NKV * HD, HIDDEN);
    sgemm_kernel<<<dim3((NKV * HD) / BN, S_LEN / BM), 256>>>(x, wv, v, S_LEN, NKV * HD, HIDDEN);

    rope_kernel<<<(S_LEN * NH * (HD / 2) + 255) / 256, 256>>>(q, NH);
    rope_kernel<<<(S_LEN * NKV * (HD / 2) + 255) / 256, 256>>>(k, NKV);

    attn_kernel<<<dim3(S_LEN / QTILE, NH), 128>>>(q, k, v, a);

    sgemm_kernel<<<dim3(HIDDEN / BN, S_LEN / BM), 256>>>(a, wo, out, S_LEN, HIDDEN, HIDDEN);
}

// round 2
// speedup vs baseline: 1.6812x; 1.6812x over previous
#include <cuda_runtime.h>
#include <math.h>
#include <stdint.h>

#define S_LEN  2048
#define HIDDEN 2048
#define NH     32
#define NKV    8
#define HD     64

// Scratch (device globals — no allocation allowed in kernel_launch)
__device__ float g_q[S_LEN * NH * HD];      // [s, h, d]
__device__ float g_k[S_LEN * NKV * HD];     // [s, kvh, d]
__device__ float g_v[S_LEN * NKV * HD];     // [s, kvh, d]
__device__ float g_attn[S_LEN * NH * HD];   // [s, h*64+d]

// ---------------------------------------------------------------------------
// TF32 tensor-core GEMM: C[M,N] = A[M,K] @ B[K,N], row-major fp32 in/out.
// Block 128x128, BK=16, 256 threads (8 warps as 4x2), warp tile 32x64,
// mma.sync.m16n8k8.tf32. Smem padded to stride 136 for conflict-free frags.
// ---------------------------------------------------------------------------
#define TBM 128
#define TBN 128
#define TBK 16
#define SPAD 136

__device__ __forceinline__ float to_tf32(float x) {
    float r;
    asm("cvt.rna.tf32.f32 %0, %1;" : "=f"(r) : "f"(x));
    return r;
}

__device__ __forceinline__ void mma_tf32(
    float& c0, float& c1, float& c2, float& c3,
    uint32_t a0, uint32_t a1, uint32_t a2, uint32_t a3,
    uint32_t b0, uint32_t b1)
{
    asm volatile(
        "mma.sync.aligned.m16n8k8.row.col.f32.tf32.tf32.f32 "
        "{%0,%1,%2,%3},{%4,%5,%6,%7},{%8,%9},{%0,%1,%2,%3};"
        : "+f"(c0), "+f"(c1), "+f"(c2), "+f"(c3)
        : "r"(a0), "r"(a1), "r"(a2), "r"(a3), "r"(b0), "r"(b1));
}

__global__ __launch_bounds__(256) void tf32_gemm_kernel(
    const float* __restrict__ A, const float* __restrict__ B,
    float* __restrict__ C, int M, int N, int K)
{
    __shared__ float As[TBK][SPAD];   // [k][m], tf32-converted
    __shared__ float Bs[TBK][SPAD];   // [k][n], tf32-converted

    const int tid  = threadIdx.x;
    const int lane = tid & 31;
    const int wid  = tid >> 5;
    const int g    = lane >> 2;       // 0..7
    const int tg   = lane & 3;        // 0..3

    const int bm = blockIdx.y * TBM;
    const int bn = blockIdx.x * TBN;
    const int warp_m = (wid >> 1) * 32;   // 0,32,64,96
    const int warp_n = (wid & 1) * 64;    // 0,64

    // Global load mapping
    const int a_row = tid >> 1;           // 0..127
    const int a_col = (tid & 1) * 8;      // 0 or 8
    const int b_row = tid >> 4;           // 0..15
    const int b_col = (tid & 15) * 8;     // 0..120

    const float* Aptr = A + (size_t)(bm + a_row) * K + a_col;
    const float* Bptr = B + (size_t)b_row * N + bn + b_col;

    float acc[2][8][4];
    #pragma unroll
    for (int mi = 0; mi < 2; ++mi)
        #pragma unroll
        for (int ni = 0; ni < 8; ++ni)
            #pragma unroll
            for (int c = 0; c < 4; ++c)
                acc[mi][ni][c] = 0.0f;

    // prefetch first tile
    float4 av0 = *(const float4*)(Aptr);
    float4 av1 = *(const float4*)(Aptr + 4);
    float4 bv0 = *(const float4*)(Bptr);
    float4 bv1 = *(const float4*)(Bptr + 4);

    for (int k0 = 0; k0 < K; k0 += TBK) {
        __syncthreads();   // previous iter's smem reads complete
        // store (tf32-convert) current tile
        As[a_col + 0][a_row] = to_tf32(av0.x);
        As[a_col + 1][a_row] = to_tf32(av0.y);
        As[a_col + 2][a_row] = to_tf32(av0.z);
        As[a_col + 3][a_row] = to_tf32(av0.w);
        As[a_col + 4][a_row] = to_tf32(av1.x);
        As[a_col + 5][a_row] = to_tf32(av1.y);
        As[a_col + 6][a_row] = to_tf32(av1.z);
        As[a_col + 7][a_row] = to_tf32(av1.w);
        Bs[b_row][b_col + 0] = to_tf32(bv0.x);
        Bs[b_row][b_col + 1] = to_tf32(bv0.y);
        Bs[b_row][b_col + 2] = to_tf32(bv0.z);
        Bs[b_row][b_col + 3] = to_tf32(bv0.w);
        Bs[b_row][b_col + 4] = to_tf32(bv1.x);
        Bs[b_row][b_col + 5] = to_tf32(bv1.y);
        Bs[b_row][b_col + 6] = to_tf32(bv1.z);
        Bs[b_row][b_col + 7] = to_tf32(bv1.w);
        __syncthreads();

        // prefetch next tile (overlaps with mma below)
        if (k0 + TBK < K) {
            av0 = *(const float4*)(Aptr + k0 + TBK);
            av1 = *(const float4*)(Aptr + k0 + TBK + 4);
            bv0 = *(const float4*)(Bptr + (size_t)(k0 + TBK) * N);
            bv1 = *(const float4*)(Bptr + (size_t)(k0 + TBK) * N + 4);
        }

        #pragma unroll
        for (int kk = 0; kk < TBK; kk += 8) {
            // A fragments for both m tiles
            uint32_t afr[2][4];
            #pragma unroll
            for (int mi = 0; mi < 2; ++mi) {
                int m0 = warp_m + mi * 16;
                afr[mi][0] = __float_as_uint(As[kk + tg    ][m0 + g    ]);
                afr[mi][1] = __float_as_uint(As[kk + tg    ][m0 + g + 8]);
                afr[mi][2] = __float_as_uint(As[kk + tg + 4][m0 + g    ]);
                afr[mi][3] = __float_as_uint(As[kk + tg + 4][m0 + g + 8]);
            }
            #pragma unroll
            for (int ni = 0; ni < 8; ++ni) {
                int n0 = warp_n + ni * 8;
                uint32_t b0 = __float_as_uint(Bs[kk + tg    ][n0 + g]);
                uint32_t b1 = __float_as_uint(Bs[kk + tg + 4][n0 + g]);
                #pragma unroll
                for (int mi = 0; mi < 2; ++mi)
                    mma_tf32(acc[mi][ni][0], acc[mi][ni][1],
                             acc[mi][ni][2], acc[mi][ni][3],
                             afr[mi][0], afr[mi][1], afr[mi][2], afr[mi][3],
                             b0, b1);
            }
        }
    }

    // Epilogue: c0,c1 at (g, tg*2, tg*2+1); c2,c3 at (g+8, ...)
    #pragma unroll
    for (int mi = 0; mi < 2; ++mi) {
        #pragma unroll
        for (int ni = 0; ni < 8; ++ni) {
            int row = bm + warp_m + mi * 16 + g;
            int col = bn + warp_n + ni * 8 + tg * 2;
            *(float2*)&C[(size_t)row * N + col] =
                make_float2(acc[mi][ni][0], acc[mi][ni][1]);
            *(float2*)&C[(size_t)(row + 8) * N + col] =
                make_float2(acc[mi][ni][2], acc[mi][ni][3]);
        }
    }
}

// ---------------------------------------------------------------------------
// RoPE (interleaved pairs), in place over x: [S, nheads, 64]
// freq table computed once per block (double, matches reference inv_freq).
// ---------------------------------------------------------------------------
__global__ void rope_kernel(float* __restrict__ x, int nheads)
{
    __shared__ float ftab[32];
    int t = threadIdx.x;
    if (t < 32)
        ftab[t] = (float)exp(-((double)t / 32.0) * log(500000.0));
    __syncthreads();

    int idx = blockIdx.x * blockDim.x + t;
    int total = S_LEN * nheads * (HD / 2);
    if (idx >= total) return;
    int i    = idx & (HD / 2 - 1);   // 0..31 pair index
    int rest = idx >> 5;
    int h    = rest % nheads;
    int s    = rest / nheads;

    float ang = (float)s * ftab[i];
    float sn, cs;
    sincosf(ang, &sn, &cs);

    float* p = x + ((size_t)s * nheads + h) * HD + 2 * i;
    float x1 = p[0], x2 = p[1];
    p[0] = x1 * cs - x2 * sn;
    p[1] = x1 * sn + x2 * cs;
}

// ---------------------------------------------------------------------------
// Causal GQA flash attention (fp32 SIMT). Grid: (S/128, 32 heads), 128 thr.
// ---------------------------------------------------------------------------
#define QTILE 128
#define KTILE 64

__global__ __launch_bounds__(128) void attn_kernel(
    const float* __restrict__ Q, const float* __restrict__ K,
    const float* __restrict__ V, float* __restrict__ O)
{
    __shared__ float Ksh[KTILE][HD];
    __shared__ float Vsh[KTILE][HD];

    const int h   = blockIdx.y;
    const int kvh = h >> 2;                 // GROUPS = 4
    const int q0  = blockIdx.x * QTILE;
    const int tid = threadIdx.x;
    const int q   = q0 + tid;

    float qreg[HD];
    const float* qptr = Q + ((size_t)q * NH + h) * HD;
    #pragma unroll
    for (int d = 0; d < HD; d += 4) {
        float4 t = *(const float4*)(qptr + d);
        qreg[d + 0] = t.x * 0.125f;
        qreg[d + 1] = t.y * 0.125f;
        qreg[d + 2] = t.z * 0.125f;
        qreg[d + 3] = t.w * 0.125f;
    }

    float m = -INFINITY, l = 0.0f;
    float4 accv[16];
    #pragma unroll
    for (int i = 0; i < 16; ++i) accv[i] = make_float4(0.f, 0.f, 0.f, 0.f);

    const int kend = q0 + QTILE;
    for (int kt = 0; kt < kend; kt += KTILE) {
        __syncthreads();
        {
            int row = tid >> 1;
            int off = (tid & 1) * 32;
            const float4* ksrc = (const float4*)(K + ((size_t)(kt + row) * NKV + kvh) * HD + off);
            const float4* vsrc = (const float4*)(V + ((size_t)(kt + row) * NKV + kvh) * HD + off);
            float4* kdst = (float4*)&Ksh[row][off];
            float4* vdst = (float4*)&Vsh[row][off];
            #pragma unroll
            for (int i = 0; i < 8; ++i) { kdst[i] = ksrc[i]; vdst[i] = vsrc[i]; }
        }
        __syncthreads();

        for (int jc = 0; jc < KTILE; jc += 16) {
            float s[16];
            float mloc = -INFINITY;
            #pragma unroll
            for (int jj = 0; jj < 16; ++jj) {
                const float4* kr = (const float4*)Ksh[jc + jj];
                float sum = 0.0f;
                #pragma unroll
                for (int d4 = 0; d4 < 16; ++d4) {
                    float4 kv = kr[d4];
                    sum += qreg[4 * d4 + 0] * kv.x;
                    sum += qreg[4 * d4 + 1] * kv.y;
                    sum += qreg[4 * d4 + 2] * kv.z;
                    sum += qreg[4 * d4 + 3] * kv.w;
                }
                s[jj] = (kt + jc + jj <= q) ? sum : -INFINITY;
                mloc  = fmaxf(mloc, s[jj]);
            }
            float mnew = fmaxf(m, mloc);
            float corr = __expf(m - mnew);
            l *= corr;
            #pragma unroll
            for (int i = 0; i < 16; ++i) {
                accv[i].x *= corr; accv[i].y *= corr;
                accv[i].z *= corr; accv[i].w *= corr;
            }
            #pragma unroll
            for (int jj = 0; jj < 16; ++jj) {
                float p = __expf(s[jj] - mnew);
                l += p;
                const float4* vr = (const float4*)Vsh[jc + jj];
                #pragma unroll
                for (int d4 = 0; d4 < 16; ++d4) {
                    float4 vv = vr[d4];
                    accv[d4].x += p * vv.x;
                    accv[d4].y += p * vv.y;
                    accv[d4].z += p * vv.z;
                    accv[d4].w += p * vv.w;
                }
            }
            m = mnew;
        }
    }

    float inv = 1.0f / l;
    float* optr = O + ((size_t)q * NH + h) * HD;
    #pragma unroll
    for (int d4 = 0; d4 < 16; ++d4) {
        float4 r;
        r.x = accv[d4].x * inv; r.y = accv[d4].y * inv;
        r.z = accv[d4].z * inv; r.w = accv[d4].w * inv;
        *(float4*)(optr + 4 * d4) = r;
    }
}

// ---------------------------------------------------------------------------
// Launch: QKV GEMMs -> RoPE(Q,K) -> attention -> output projection
// ---------------------------------------------------------------------------
extern "C" void kernel_launch(void* const* d_in, const int* in_sizes, int n_in,
                              void* d_out, int out_size)
{
    const float* x  = (const float*)d_in[0];
    const float* wq = (const float*)d_in[2];
    const float* wk = (const float*)d_in[3];
    const float* wv = (const float*)d_in[4];
    const float* wo = (const float*)d_in[5];
    float* out = (float*)d_out;

    float *q, *k, *v, *a;
    cudaGetSymbolAddress((void**)&q, g_q);
    cudaGetSymbolAddress((void**)&k, g_k);
    cudaGetSymbolAddress((void**)&v, g_v);
    cudaGetSymbolAddress((void**)&a, g_attn);

    tf32_gemm_kernel<<<dim3((NH * HD) / TBN, S_LEN / TBM), 256>>>(x, wq, q, S_LEN, NH * HD, HIDDEN);
    tf32_gemm_kernel<<<dim3((NKV * HD) / TBN, S_LEN / TBM), 256>>>(x, wk, k, S_LEN, NKV * HD, HIDDEN);
    tf32_gemm_kernel<<<dim3((NKV * HD) / TBN, S_LEN / TBM), 256>>>(x, wv, v, S_LEN, NKV * HD, HIDDEN);

    rope_kernel<<<(S_LEN * NH * (HD / 2) + 255) / 256, 256>>>(q, NH);
    rope_kernel<<<(S_LEN * NKV * (HD / 2) + 255) / 256, 256>>>(k, NKV);

    attn_kernel<<<dim3(S_LEN / QTILE, NH), 128>>>(q, k, v, a);

    tf32_gemm_kernel<<<dim3(HIDDEN / TBN, S_LEN / TBM), 256>>>(a, wo, out, S_LEN, HIDDEN, HIDDEN);
}

// round 3
// speedup vs baseline: 3.4093x; 2.0279x over previous
#include <cuda_runtime.h>
#include <math.h>
#include <stdint.h>

#define S_LEN  2048
#define HIDDEN 2048
#define NH     32
#define NKV    8
#define HD     64

// Scratch (device globals — no allocation allowed in kernel_launch)
__device__ float g_q[S_LEN * NH * HD];      // [s, h, d]
__device__ float g_k[S_LEN * NKV * HD];     // [s, kvh, d]
__device__ float g_v[S_LEN * NKV * HD];     // [s, kvh, d]
__device__ float g_attn[S_LEN * NH * HD];   // [s, h*64+d]

__device__ __forceinline__ float to_tf32(float x) {
    float r;
    asm("cvt.rna.tf32.f32 %0, %1;" : "=f"(r) : "f"(x));
    return r;
}

__device__ __forceinline__ void mma_tf32(
    float& c0, float& c1, float& c2, float& c3,
    uint32_t a0, uint32_t a1, uint32_t a2, uint32_t a3,
    uint32_t b0, uint32_t b1)
{
    asm volatile(
        "mma.sync.aligned.m16n8k8.row.col.f32.tf32.tf32.f32 "
        "{%0,%1,%2,%3},{%4,%5,%6,%7},{%8,%9},{%0,%1,%2,%3};"
        : "+f"(c0), "+f"(c1), "+f"(c2), "+f"(c3)
        : "r"(a0), "r"(a1), "r"(a2), "r"(a3), "r"(b0), "r"(b1));
}

// ---------------------------------------------------------------------------
// TF32 tensor-core GEMM: C[M,N] = A[M,K] @ B[K,N], row-major fp32 in/out.
// Block 128x128, BK=16, 256 threads (8 warps as 4x2), warp tile 32x64.
// ROPE=1: apply interleaved RoPE to the output (row = seq pos, col%64 = dim).
// ---------------------------------------------------------------------------
#define TBM 128
#define TBN 128
#define TBK 16
#define SPAD 136

// log2(500000)/32
#define L2T_OVER_32 0.5916115177913804f

template<int ROPE>
__global__ __launch_bounds__(256) void tf32_gemm_kernel(
    const float* __restrict__ A, const float* __restrict__ B,
    float* __restrict__ C, int M, int N, int K)
{
    __shared__ float As[TBK][SPAD];   // [k][m], tf32-converted
    __shared__ float Bs[TBK][SPAD];   // [k][n], tf32-converted

    const int tid  = threadIdx.x;
    const int lane = tid & 31;
    const int wid  = tid >> 5;
    const int g    = lane >> 2;       // 0..7
    const int tg   = lane & 3;        // 0..3

    const int bm = blockIdx.y * TBM;
    const int bn = blockIdx.x * TBN;
    const int warp_m = (wid >> 1) * 32;   // 0,32,64,96
    const int warp_n = (wid & 1) * 64;    // 0,64

    const int a_row = tid >> 1;           // 0..127
    const int a_col = (tid & 1) * 8;      // 0 or 8
    const int b_row = tid >> 4;           // 0..15
    const int b_col = (tid & 15) * 8;     // 0..120

    const float* Aptr = A + (size_t)(bm + a_row) * K + a_col;
    const float* Bptr = B + (size_t)b_row * N + bn + b_col;

    float acc[2][8][4];
    #pragma unroll
    for (int mi = 0; mi < 2; ++mi)
        #pragma unroll
        for (int ni = 0; ni < 8; ++ni)
            #pragma unroll
            for (int c = 0; c < 4; ++c)
                acc[mi][ni][c] = 0.0f;

    float4 av0 = *(const float4*)(Aptr);
    float4 av1 = *(const float4*)(Aptr + 4);
    float4 bv0 = *(const float4*)(Bptr);
    float4 bv1 = *(const float4*)(Bptr + 4);

    for (int k0 = 0; k0 < K; k0 += TBK) {
        __syncthreads();
        As[a_col + 0][a_row] = to_tf32(av0.x);
        As[a_col + 1][a_row] = to_tf32(av0.y);
        As[a_col + 2][a_row] = to_tf32(av0.z);
        As[a_col + 3][a_row] = to_tf32(av0.w);
        As[a_col + 4][a_row] = to_tf32(av1.x);
        As[a_col + 5][a_row] = to_tf32(av1.y);
        As[a_col + 6][a_row] = to_tf32(av1.z);
        As[a_col + 7][a_row] = to_tf32(av1.w);
        Bs[b_row][b_col + 0] = to_tf32(bv0.x);
        Bs[b_row][b_col + 1] = to_tf32(bv0.y);
        Bs[b_row][b_col + 2] = to_tf32(bv0.z);
        Bs[b_row][b_col + 3] = to_tf32(bv0.w);
        Bs[b_row][b_col + 4] = to_tf32(bv1.x);
        Bs[b_row][b_col + 5] = to_tf32(bv1.y);
        Bs[b_row][b_col + 6] = to_tf32(bv1.z);
        Bs[b_row][b_col + 7] = to_tf32(bv1.w);
        __syncthreads();

        if (k0 + TBK < K) {
            av0 = *(const float4*)(Aptr + k0 + TBK);
            av1 = *(const float4*)(Aptr + k0 + TBK + 4);
            bv0 = *(const float4*)(Bptr + (size_t)(k0 + TBK) * N);
            bv1 = *(const float4*)(Bptr + (size_t)(k0 + TBK) * N + 4);
        }

        #pragma unroll
        for (int kk = 0; kk < TBK; kk += 8) {
            uint32_t afr[2][4];
            #pragma unroll
            for (int mi = 0; mi < 2; ++mi) {
                int m0 = warp_m + mi * 16;
                afr[mi][0] = __float_as_uint(As[kk + tg    ][m0 + g    ]);
                afr[mi][1] = __float_as_uint(As[kk + tg    ][m0 + g + 8]);
                afr[mi][2] = __float_as_uint(As[kk + tg + 4][m0 + g    ]);
                afr[mi][3] = __float_as_uint(As[kk + tg + 4][m0 + g + 8]);
            }
            #pragma unroll
            for (int ni = 0; ni < 8; ++ni) {
                int n0 = warp_n + ni * 8;
                uint32_t b0 = __float_as_uint(Bs[kk + tg    ][n0 + g]);
                uint32_t b1 = __float_as_uint(Bs[kk + tg + 4][n0 + g]);
                #pragma unroll
                for (int mi = 0; mi < 2; ++mi)
                    mma_tf32(acc[mi][ni][0], acc[mi][ni][1],
                             acc[mi][ni][2], acc[mi][ni][3],
                             afr[mi][0], afr[mi][1], afr[mi][2], afr[mi][3],
                             b0, b1);
            }
        }
    }

    #pragma unroll
    for (int mi = 0; mi < 2; ++mi) {
        #pragma unroll
        for (int ni = 0; ni < 8; ++ni) {
            int row = bm + warp_m + mi * 16 + g;
            int col = bn + warp_n + ni * 8 + tg * 2;
            float c0 = acc[mi][ni][0], c1 = acc[mi][ni][1];
            float c2 = acc[mi][ni][2], c3 = acc[mi][ni][3];
            if (ROPE) {
                int i = (col & 63) >> 1;           // rope pair index 0..31
                float freq = exp2f(-(float)i * L2T_OVER_32);
                float sn0, cs0, sn1, cs1;
                sincosf((float)row * freq, &sn0, &cs0);
                sincosf((float)(row + 8) * freq, &sn1, &cs1);
                float r0 = c0 * cs0 - c1 * sn0;
                float r1 = c0 * sn0 + c1 * cs0;
                float r2 = c2 * cs1 - c3 * sn1;
                float r3 = c2 * sn1 + c3 * cs1;
                c0 = r0; c1 = r1; c2 = r2; c3 = r3;
            }
            *(float2*)&C[(size_t)row * N + col]       = make_float2(c0, c1);
            *(float2*)&C[(size_t)(row + 8) * N + col] = make_float2(c2, c3);
        }
    }
}

// ---------------------------------------------------------------------------
// Causal GQA flash attention with TF32 tensor cores.
// Block: 128 q-rows x 1 head, 8 warps (16 rows each), 64-key tiles.
// Dynamic smem: Ksm[64][72] (K^T), Vsm[64][72], Psm[64][136] (P^T / Q^T stage).
// ---------------------------------------------------------------------------
#define AQT 128
#define AKT 64
#define KSTR 72     // 72 % 32 == 8 -> conflict-free frag loads
#define PSTR 136    // 136 % 32 == 8
#define ASMEM ((2 * 64 * KSTR + 64 * PSTR) * 4)

__global__ __launch_bounds__(256) void attn_mma_kernel(
    const float* __restrict__ Qg, const float* __restrict__ Kg,
    const float* __restrict__ Vg, float* __restrict__ Og)
{
    extern __shared__ float sm[];
    float* Ksm = sm;                    // [d=64][KSTR] keys in columns
    float* Vsm = sm + 64 * KSTR;        // [key=64][KSTR] dims in columns
    float* Psm = sm + 2 * 64 * KSTR;    // [key=64][PSTR] qrows in columns (also Q^T stage)

    const int h    = blockIdx.y;
    const int kvh  = h >> 2;
    const int qt   = gridDim.x - 1 - blockIdx.x;   // heavy tiles first
    const int q0   = qt * AQT;
    const int tid  = threadIdx.x;
    const int lane = tid & 31;
    const int wid  = tid >> 5;          // 0..7
    const int g    = lane >> 2;         // 0..7
    const int tg   = lane & 3;          // 0..3
    const int warp_m = wid * 16;

    // ---- stage Q (scaled by 1/8, tf32) transposed into Psm ----
    {
        int r  = tid >> 1;
        int cb = (tid & 1) * 32;
        const float* src = Qg + ((size_t)(q0 + r) * NH + h) * HD + cb;
        #pragma unroll
        for (int j = 0; j < 32; j += 4) {
            float4 t = *(const float4*)(src + j);
            Psm[(cb + j + 0) * PSTR + r] = to_tf32(t.x * 0.125f);
            Psm[(cb + j + 1) * PSTR + r] = to_tf32(t.y * 0.125f);
            Psm[(cb + j + 2) * PSTR + r] = to_tf32(t.z * 0.125f);
            Psm[(cb + j + 3) * PSTR + r] = to_tf32(t.w * 0.125f);
        }
    }
    __syncthreads();

    // Q A-fragments (8 k-steps x 4 regs), warp-private columns of Psm
    uint32_t qf[8][4];
    #pragma unroll
    for (int ks = 0; ks < 8; ++ks) {
        qf[ks][0] = __float_as_uint(Psm[(ks * 8 + tg    ) * PSTR + warp_m + g    ]);
        qf[ks][1] = __float_as_uint(Psm[(ks * 8 + tg    ) * PSTR + warp_m + g + 8]);
        qf[ks][2] = __float_as_uint(Psm[(ks * 8 + tg + 4) * PSTR + warp_m + g    ]);
        qf[ks][3] = __float_as_uint(Psm[(ks * 8 + tg + 4) * PSTR + warp_m + g + 8]);
    }

    float m0 = -INFINITY, m1 = -INFINITY, l0 = 0.0f, l1 = 0.0f;
    float o[8][4];
    #pragma unroll
    for (int ni = 0; ni < 8; ++ni)
        #pragma unroll
        for (int c = 0; c < 4; ++c) o[ni][c] = 0.0f;

    const int ntiles = (q0 + AQT) / AKT;
    for (int t = 0; t < ntiles; ++t) {
        const int kt = t * AKT;
        __syncthreads();   // prior tile fully consumed (and Q frags extracted)
        {
            int r  = tid >> 2;
            int cb = (tid & 3) * 16;
            const float* ks = Kg + ((size_t)(kt + r) * NKV + kvh) * HD + cb;
            const float* vs = Vg + ((size_t)(kt + r) * NKV + kvh) * HD + cb;
            #pragma unroll
            for (int j = 0; j < 16; j += 4) {
                float4 a = *(const float4*)(ks + j);
                Ksm[(cb + j + 0) * KSTR + r] = to_tf32(a.x);
                Ksm[(cb + j + 1) * KSTR + r] = to_tf32(a.y);
                Ksm[(cb + j + 2) * KSTR + r] = to_tf32(a.z);
                Ksm[(cb + j + 3) * KSTR + r] = to_tf32(a.w);
                float4 b = *(const float4*)(vs + j);
                *(float4*)&Vsm[r * KSTR + cb + j] = make_float4(
                    to_tf32(b.x), to_tf32(b.y), to_tf32(b.z), to_tf32(b.w));
            }
        }
        __syncthreads();

        // ---- S = Q @ K^T (scores) ----
        float sc[8][4];
        #pragma unroll
        for (int ni = 0; ni < 8; ++ni) {
            sc[ni][0] = sc[ni][1] = sc[ni][2] = sc[ni][3] = 0.0f;
            #pragma unroll
            for (int ks = 0; ks < 8; ++ks) {
                uint32_t b0 = __float_as_uint(Ksm[(ks * 8 + tg    ) * KSTR + ni * 8 + g]);
                uint32_t b1 = __float_as_uint(Ksm[(ks * 8 + tg + 4) * KSTR + ni * 8 + g]);
                mma_tf32(sc[ni][0], sc[ni][1], sc[ni][2], sc[ni][3],
                         qf[ks][0], qf[ks][1], qf[ks][2], qf[ks][3], b0, b1);
            }
        }

        // ---- causal mask (only tiles overlapping the diagonal) ----
        const int row0 = q0 + warp_m + g;
        const int row1 = row0 + 8;
        if (kt + AKT - 1 > q0 + warp_m) {
            #pragma unroll
            for (int ni = 0; ni < 8; ++ni) {
                int col = kt + ni * 8 + tg * 2;
                if (col     > row0) sc[ni][0] = -INFINITY;
                if (col + 1 > row0) sc[ni][1] = -INFINITY;
                if (col     > row1) sc[ni][2] = -INFINITY;
                if (col + 1 > row1) sc[ni][3] = -INFINITY;
            }
        }

        // ---- online softmax (rows row0 and row1, spread over tg lanes) ----
        float mx0 = -INFINITY, mx1 = -INFINITY;
        #pragma unroll
        for (int ni = 0; ni < 8; ++ni) {
            mx0 = fmaxf(mx0, fmaxf(sc[ni][0], sc[ni][1]));
            mx1 = fmaxf(mx1, fmaxf(sc[ni][2], sc[ni][3]));
        }
        mx0 = fmaxf(mx0, __shfl_xor_sync(0xffffffffu, mx0, 1));
        mx0 = fmaxf(mx0, __shfl_xor_sync(0xffffffffu, mx0, 2));
        mx1 = fmaxf(mx1, __shfl_xor_sync(0xffffffffu, mx1, 1));
        mx1 = fmaxf(mx1, __shfl_xor_sync(0xffffffffu, mx1, 2));

        float mn0 = fmaxf(m0, mx0), mn1 = fmaxf(m1, mx1);
        float cr0 = __expf(m0 - mn0), cr1 = __expf(m1 - mn1);
        m0 = mn0; m1 = mn1;

        float s0 = 0.0f, s1 = 0.0f;
        #pragma unroll
        for (int ni = 0; ni < 8; ++ni) {
            sc[ni][0] = __expf(sc[ni][0] - mn0); s0 += sc[ni][0];
            sc[ni][1] = __expf(sc[ni][1] - mn0); s0 += sc[ni][1];
            sc[ni][2] = __expf(sc[ni][2] - mn1); s1 += sc[ni][2];
            sc[ni][3] = __expf(sc[ni][3] - mn1); s1 += sc[ni][3];
        }
        s0 += __shfl_xor_sync(0xffffffffu, s0, 1);
        s0 += __shfl_xor_sync(0xffffffffu, s0, 2);
        s1 += __shfl_xor_sync(0xffffffffu, s1, 1);
        s1 += __shfl_xor_sync(0xffffffffu, s1, 2);
        l0 = l0 * cr0 + s0;
        l1 = l1 * cr1 + s1;

        // ---- store P^T (tf32) into warp-private Psm columns ----
        #pragma unroll
        for (int ni = 0; ni < 8; ++ni) {
            int cb = (ni * 8 + tg * 2) * PSTR;
            Psm[cb        + warp_m + g    ] = to_tf32(sc[ni][0]);
            Psm[cb + PSTR + warp_m + g    ] = to_tf32(sc[ni][1]);
            Psm[cb        + warp_m + g + 8] = to_tf32(sc[ni][2]);
            Psm[cb + PSTR + warp_m + g + 8] = to_tf32(sc[ni][3]);
        }
        __syncwarp();

        // ---- rescale O ----
        #pragma unroll
        for (int ni = 0; ni < 8; ++ni) {
            o[ni][0] *= cr0; o[ni][1] *= cr0;
            o[ni][2] *= cr1; o[ni][3] *= cr1;
        }

        // ---- O += P @ V ----
        #pragma unroll
        for (int ks = 0; ks < 8; ++ks) {
            uint32_t pa0 = __float_as_uint(Psm[(ks * 8 + tg    ) * PSTR + warp_m + g    ]);
            uint32_t pa1 = __float_as_uint(Psm[(ks * 8 + tg    ) * PSTR + warp_m + g + 8]);
            uint32_t pa2 = __float_as_uint(Psm[(ks * 8 + tg + 4) * PSTR + warp_m + g    ]);
            uint32_t pa3 = __float_as_uint(Psm[(ks * 8 + tg + 4) * PSTR + warp_m + g + 8]);
            #pragma unroll
            for (int ni = 0; ni < 8; ++ni) {
                uint32_t b0 = __float_as_uint(Vsm[(ks * 8 + tg    ) * KSTR + ni * 8 + g]);
                uint32_t b1 = __float_as_uint(Vsm[(ks * 8 + tg + 4) * KSTR + ni * 8 + g]);
                mma_tf32(o[ni][0], o[ni][1], o[ni][2], o[ni][3],
                         pa0, pa1, pa2, pa3, b0, b1);
            }
        }
    }

    // ---- normalize and write O ----
    float inv0 = 1.0f / l0, inv1 = 1.0f / l1;
    const int row0 = q0 + warp_m + g;
    #pragma unroll
    for (int ni = 0; ni < 8; ++ni) {
        int col = ni * 8 + tg * 2;
        *(float2*)&Og[((size_t)row0 * NH + h) * HD + col] =
            make_float2(o[ni][0] * inv0, o[ni][1] * inv0);
        *(float2*)&Og[((size_t)(row0 + 8) * NH + h) * HD + col] =
            make_float2(o[ni][2] * inv1, o[ni][3] * inv1);
    }
}

// ---------------------------------------------------------------------------
// Launch: QKV GEMMs (RoPE fused into Q,K) -> attention -> output projection
// ---------------------------------------------------------------------------
extern "C" void kernel_launch(void* const* d_in, const int* in_sizes, int n_in,
                              void* d_out, int out_size)
{
    const float* x  = (const float*)d_in[0];
    const float* wq = (const float*)d_in[2];
    const float* wk = (const float*)d_in[3];
    const float* wv = (const float*)d_in[4];
    const float* wo = (const float*)d_in[5];
    float* out = (float*)d_out;

    float *q, *k, *v, *a;
    cudaGetSymbolAddress((void**)&q, g_q);
    cudaGetSymbolAddress((void**)&k, g_k);
    cudaGetSymbolAddress((void**)&v, g_v);
    cudaGetSymbolAddress((void**)&a, g_attn);

    cudaFuncSetAttribute(attn_mma_kernel,
                         cudaFuncAttributeMaxDynamicSharedMemorySize, ASMEM);

    tf32_gemm_kernel<1><<<dim3((NH * HD) / TBN, S_LEN / TBM), 256>>>(x, wq, q, S_LEN, NH * HD, HIDDEN);
    tf32_gemm_kernel<1><<<dim3((NKV * HD) / TBN, S_LEN / TBM), 256>>>(x, wk, k, S_LEN, NKV * HD, HIDDEN);
    tf32_gemm_kernel<0><<<dim3((NKV * HD) / TBN, S_LEN / TBM), 256>>>(x, wv, v, S_LEN, NKV * HD, HIDDEN);

    attn_mma_kernel<<<dim3(S_LEN / AQT, NH), 256, ASMEM>>>(q, k, v, a);

    tf32_gemm_kernel<0><<<dim3(HIDDEN / TBN, S_LEN / TBM), 256>>>(a, wo, out, S_LEN, HIDDEN, HIDDEN);
}

// round 4
// speedup vs baseline: 3.6849x; 1.0808x over previous
#include <cuda_runtime.h>
#include <math.h>
#include <stdint.h>

#define S_LEN  2048
#define HIDDEN 2048
#define NH     32
#define NKV    8
#define HD     64

// Scratch (device globals — no allocation allowed in kernel_launch)
__device__ float g_q[S_LEN * NH * HD];      // [s, h, d]
__device__ float g_k[S_LEN * NKV * HD];     // [s, kvh, d]
__device__ float g_v[S_LEN * NKV * HD];     // [s, kvh, d]
__device__ float g_attn[S_LEN * NH * HD];   // [s, h*64+d]

__device__ __forceinline__ float to_tf32(float x) {
    float r;
    asm("cvt.rna.tf32.f32 %0, %1;" : "=f"(r) : "f"(x));
    return r;
}

__device__ __forceinline__ void mma_tf32(
    float& c0, float& c1, float& c2, float& c3,
    uint32_t a0, uint32_t a1, uint32_t a2, uint32_t a3,
    uint32_t b0, uint32_t b1)
{
    asm volatile(
        "mma.sync.aligned.m16n8k8.row.col.f32.tf32.tf32.f32 "
        "{%0,%1,%2,%3},{%4,%5,%6,%7},{%8,%9},{%0,%1,%2,%3};"
        : "+f"(c0), "+f"(c1), "+f"(c2), "+f"(c3)
        : "r"(a0), "r"(a1), "r"(a2), "r"(a3), "r"(b0), "r"(b1));
}

// ---------------------------------------------------------------------------
// TF32 GEMM core: C[2048, N] = A[2048, 2048] @ B[2048, N], row-major fp32.
// Block tile 128x128, BK=16, 256 threads (8 warps 4x2), warp tile 32x64.
// Smem layout: [row][kslot16], slot(k) = (k&3)*4 + (k>>2), 4-float group
// XOR-swizzled by (row>>1)&3 -> every fragment load is one LDS.128,
// conflict-free. Double-buffered (2 stages), LDG(t+1) overlaps mma(t).
// ---------------------------------------------------------------------------
#define NTILES (HIDDEN / 16)

// log2(500000)/32
#define L2T_OVER_32 0.5916115177913804f

__device__ __forceinline__ int swz_idx(int row, int k) {
    return row * 16 + ((((k) & 3) ^ ((row >> 1) & 3)) << 2) + ((k) >> 2);
}

__device__ __forceinline__ void gemm_core(
    const float* __restrict__ A, const float* __restrict__ B,
    float* __restrict__ C, int N, int bm, int bn, int rope,
    float* sA, float* sB)
{
    const int tid  = threadIdx.x;
    const int lane = tid & 31;
    const int wid  = tid >> 5;
    const int g    = lane >> 2;       // 0..7
    const int tg   = lane & 3;        // 0..3
    const int warp_m = (wid >> 1) * 32;   // 0,32,64,96
    const int warp_n = (wid & 1) * 64;    // 0,64

    // Global->smem mapping
    const int a_row = tid >> 1;           // 0..127
    const int a_col = (tid & 1) * 8;      // 0 or 8
    const int b_n   = tid & 127;          // 0..127
    const int b_k   = (tid >> 7) * 8;     // 0 or 8

    const float* Ap = A + (size_t)(bm + a_row) * HIDDEN + a_col;
    const float* Bp = B + (size_t)b_k * N + bn + b_n;

    float acc[2][8][4];
    #pragma unroll
    for (int mi = 0; mi < 2; ++mi)
        #pragma unroll
        for (int ni = 0; ni < 8; ++ni)
            #pragma unroll
            for (int c = 0; c < 4; ++c)
                acc[mi][ni][c] = 0.0f;

    float ar[8], br[8];
    // ---- load tile 0 ----
    {
        float4 v0 = *(const float4*)(Ap);
        float4 v1 = *(const float4*)(Ap + 4);
        ar[0]=v0.x; ar[1]=v0.y; ar[2]=v0.z; ar[3]=v0.w;
        ar[4]=v1.x; ar[5]=v1.y; ar[6]=v1.z; ar[7]=v1.w;
        #pragma unroll
        for (int j = 0; j < 8; ++j) br[j] = Bp[(size_t)j * N];
    }
    #pragma unroll
    for (int j = 0; j < 8; ++j) sA[swz_idx(a_row, a_col + j)] = to_tf32(ar[j]);
    #pragma unroll
    for (int j = 0; j < 8; ++j) sB[swz_idx(b_n, b_k + j)] = to_tf32(br[j]);
    __syncthreads();

    const int fswz = ((g >> 1) & 3);          // fragment-load group xor
    const int foff = ((tg ^ fswz) << 2);      // float4 offset within row

    for (int t = 0; t < NTILES; ++t) {
        const int cur = t & 1;

        // ---- prefetch tile t+1 into registers ----
        if (t + 1 < NTILES) {
            const float* Ap2 = Ap + (t + 1) * 16;
            float4 v0 = *(const float4*)(Ap2);
            float4 v1 = *(const float4*)(Ap2 + 4);
            ar[0]=v0.x; ar[1]=v0.y; ar[2]=v0.z; ar[3]=v0.w;
            ar[4]=v1.x; ar[5]=v1.y; ar[6]=v1.z; ar[7]=v1.w;
            const float* Bp2 = Bp + (size_t)(t + 1) * 16 * N;
            #pragma unroll
            for (int j = 0; j < 8; ++j) br[j] = Bp2[(size_t)j * N];
        }

        // ---- mma over stage cur (one 16-k chunk) ----
        const float* As = sA + cur * 2048;
        const float* Bs = sB + cur * 2048;

        float4 alo[2], ahi[2];
        #pragma unroll
        for (int mi = 0; mi < 2; ++mi) {
            int r0 = warp_m + mi * 16 + g;
            alo[mi] = *(const float4*)&As[r0 * 16 + foff];
            ahi[mi] = *(const float4*)&As[(r0 + 8) * 16 + foff];
        }
        #pragma unroll
        for (int ni = 0; ni < 8; ++ni) {
            int nr = warp_n + ni * 8 + g;
            float4 bv = *(const float4*)&Bs[nr * 16 + foff];
            #pragma unroll
            for (int mi = 0; mi < 2; ++mi) {
                mma_tf32(acc[mi][ni][0], acc[mi][ni][1],
                         acc[mi][ni][2], acc[mi][ni][3],
                         __float_as_uint(alo[mi].x), __float_as_uint(ahi[mi].x),
                         __float_as_uint(alo[mi].y), __float_as_uint(ahi[mi].y),
                         __float_as_uint(bv.x), __float_as_uint(bv.y));
                mma_tf32(acc[mi][ni][0], acc[mi][ni][1],
                         acc[mi][ni][2], acc[mi][ni][3],
                         __float_as_uint(alo[mi].z), __float_as_uint(ahi[mi].z),
                         __float_as_uint(alo[mi].w), __float_as_uint(ahi[mi].w),
                         __float_as_uint(bv.z), __float_as_uint(bv.w));
            }
        }

        __syncthreads();   // all warps done reading stage (t+1)&1 (at iter t-1)
        if (t + 1 < NTILES) {
            float* nA = sA + ((t + 1) & 1) * 2048;
            float* nB = sB + ((t + 1) & 1) * 2048;
            #pragma unroll
            for (int j = 0; j < 8; ++j) nA[swz_idx(a_row, a_col + j)] = to_tf32(ar[j]);
            #pragma unroll
            for (int j = 0; j < 8; ++j) nB[swz_idx(b_n, b_k + j)] = to_tf32(br[j]);
        }
        __syncthreads();   // stage (t+1)&1 visible for next iter's mma
    }

    // ---- epilogue (optional fused RoPE: row = seq pos, col%64 = dim) ----
    #pragma unroll
    for (int mi = 0; mi < 2; ++mi) {
        #pragma unroll
        for (int ni = 0; ni < 8; ++ni) {
            int row = bm + warp_m + mi * 16 + g;
            int col = bn + warp_n + ni * 8 + tg * 2;
            float c0 = acc[mi][ni][0], c1 = acc[mi][ni][1];
            float c2 = acc[mi][ni][2], c3 = acc[mi][ni][3];
            if (rope) {
                int i = (col & 63) >> 1;
                float freq = exp2f(-(float)i * L2T_OVER_32);
                float sn0, cs0, sn1, cs1;
                sincosf((float)row * freq, &sn0, &cs0);
                sincosf((float)(row + 8) * freq, &sn1, &cs1);
                float r0 = c0 * cs0 - c1 * sn0;
                float r1 = c0 * sn0 + c1 * cs0;
                float r2 = c2 * cs1 - c3 * sn1;
                float r3 = c2 * sn1 + c3 * cs1;
                c0 = r0; c1 = r1; c2 = r2; c3 = r3;
            }
            *(float2*)&C[(size_t)row * N + col]       = make_float2(c0, c1);
            *(float2*)&C[(size_t)(row + 8) * N + col] = make_float2(c2, c3);
        }
    }
}

// Fused QKV projection: blockIdx.x 0..23 selects matrix + column tile.
__global__ __launch_bounds__(256) void qkv_gemm_kernel(
    const float* __restrict__ x,
    const float* __restrict__ wq, const float* __restrict__ wk,
    const float* __restrict__ wv,
    float* __restrict__ q, float* __restrict__ k, float* __restrict__ v)
{
    __shared__ float sA[2 * 2048];
    __shared__ float sB[2 * 2048];
    const int bx = blockIdx.x;
    const float* B; float* C; int N, bn, rope;
    if (bx < 16)      { B = wq; C = q; N = NH * HD;  bn = bx * 128;        rope = 1; }
    else if (bx < 20) { B = wk; C = k; N = NKV * HD; bn = (bx - 16) * 128; rope = 1; }
    else              { B = wv; C = v; N = NKV * HD; bn = (bx - 20) * 128; rope = 0; }
    gemm_core(x, B, C, N, blockIdx.y * 128, bn, rope, sA, sB);
}

__global__ __launch_bounds__(256) void out_gemm_kernel(
    const float* __restrict__ a, const float* __restrict__ w,
    float* __restrict__ out)
{
    __shared__ float sA[2 * 2048];
    __shared__ float sB[2 * 2048];
    gemm_core(a, w, out, HIDDEN, blockIdx.y * 128, blockIdx.x * 128, 0, sA, sB);
}

// ---------------------------------------------------------------------------
// Causal GQA flash attention with TF32 tensor cores (unchanged from round 3).
// ---------------------------------------------------------------------------
#define AQT 128
#define AKT 64
#define KSTR 72
#define PSTR 136
#define ASMEM ((2 * 64 * KSTR + 64 * PSTR) * 4)

__global__ __launch_bounds__(256) void attn_mma_kernel(
    const float* __restrict__ Qg, const float* __restrict__ Kg,
    const float* __restrict__ Vg, float* __restrict__ Og)
{
    extern __shared__ float sm[];
    float* Ksm = sm;
    float* Vsm = sm + 64 * KSTR;
    float* Psm = sm + 2 * 64 * KSTR;

    const int h    = blockIdx.y;
    const int kvh  = h >> 2;
    const int qt   = gridDim.x - 1 - blockIdx.x;
    const int q0   = qt * AQT;
    const int tid  = threadIdx.x;
    const int lane = tid & 31;
    const int wid  = tid >> 5;
    const int g    = lane >> 2;
    const int tg   = lane & 3;
    const int warp_m = wid * 16;

    {
        int r  = tid >> 1;
        int cb = (tid & 1) * 32;
        const float* src = Qg + ((size_t)(q0 + r) * NH + h) * HD + cb;
        #pragma unroll
        for (int j = 0; j < 32; j += 4) {
            float4 t = *(const float4*)(src + j);
            Psm[(cb + j + 0) * PSTR + r] = to_tf32(t.x * 0.125f);
            Psm[(cb + j + 1) * PSTR + r] = to_tf32(t.y * 0.125f);
            Psm[(cb + j + 2) * PSTR + r] = to_tf32(t.z * 0.125f);
            Psm[(cb + j + 3) * PSTR + r] = to_tf32(t.w * 0.125f);
        }
    }
    __syncthreads();

    uint32_t qf[8][4];
    #pragma unroll
    for (int ks = 0; ks < 8; ++ks) {
        qf[ks][0] = __float_as_uint(Psm[(ks * 8 + tg    ) * PSTR + warp_m + g    ]);
        qf[ks][1] = __float_as_uint(Psm[(ks * 8 + tg    ) * PSTR + warp_m + g + 8]);
        qf[ks][2] = __float_as_uint(Psm[(ks * 8 + tg + 4) * PSTR + warp_m + g    ]);
        qf[ks][3] = __float_as_uint(Psm[(ks * 8 + tg + 4) * PSTR + warp_m + g + 8]);
    }

    float m0 = -INFINITY, m1 = -INFINITY, l0 = 0.0f, l1 = 0.0f;
    float o[8][4];
    #pragma unroll
    for (int ni = 0; ni < 8; ++ni)
        #pragma unroll
        for (int c = 0; c < 4; ++c) o[ni][c] = 0.0f;

    const int ntiles = (q0 + AQT) / AKT;
    for (int t = 0; t < ntiles; ++t) {
        const int kt = t * AKT;
        __syncthreads();
        {
            int r  = tid >> 2;
            int cb = (tid & 3) * 16;
            const float* ks = Kg + ((size_t)(kt + r) * NKV + kvh) * HD + cb;
            const float* vs = Vg + ((size_t)(kt + r) * NKV + kvh) * HD + cb;
            #pragma unroll
            for (int j = 0; j < 16; j += 4) {
                float4 a = *(const float4*)(ks + j);
                Ksm[(cb + j + 0) * KSTR + r] = to_tf32(a.x);
                Ksm[(cb + j + 1) * KSTR + r] = to_tf32(a.y);
                Ksm[(cb + j + 2) * KSTR + r] = to_tf32(a.z);
                Ksm[(cb + j + 3) * KSTR + r] = to_tf32(a.w);
                float4 b = *(const float4*)(vs + j);
                *(float4*)&Vsm[r * KSTR + cb + j] = make_float4(
                    to_tf32(b.x), to_tf32(b.y), to_tf32(b.z), to_tf32(b.w));
            }
        }
        __syncthreads();

        float sc[8][4];
        #pragma unroll
        for (int ni = 0; ni < 8; ++ni) {
            sc[ni][0] = sc[ni][1] = sc[ni][2] = sc[ni][3] = 0.0f;
            #pragma unroll
            for (int ks = 0; ks < 8; ++ks) {
                uint32_t b0 = __float_as_uint(Ksm[(ks * 8 + tg    ) * KSTR + ni * 8 + g]);
                uint32_t b1 = __float_as_uint(Ksm[(ks * 8 + tg + 4) * KSTR + ni * 8 + g]);
                mma_tf32(sc[ni][0], sc[ni][1], sc[ni][2], sc[ni][3],
                         qf[ks][0], qf[ks][1], qf[ks][2], qf[ks][3], b0, b1);
            }
        }

        const int row0 = q0 + warp_m + g;
        const int row1 = row0 + 8;
        if (kt + AKT - 1 > q0 + warp_m) {
            #pragma unroll
            for (int ni = 0; ni < 8; ++ni) {
                int col = kt + ni * 8 + tg * 2;
                if (col     > row0) sc[ni][0] = -INFINITY;
                if (col + 1 > row0) sc[ni][1] = -INFINITY;
                if (col     > row1) sc[ni][2] = -INFINITY;
                if (col + 1 > row1) sc[ni][3] = -INFINITY;
            }
        }

        float mx0 = -INFINITY, mx1 = -INFINITY;
        #pragma unroll
        for (int ni = 0; ni < 8; ++ni) {
            mx0 = fmaxf(mx0, fmaxf(sc[ni][0], sc[ni][1]));
            mx1 = fmaxf(mx1, fmaxf(sc[ni][2], sc[ni][3]));
        }
        mx0 = fmaxf(mx0, __shfl_xor_sync(0xffffffffu, mx0, 1));
        mx0 = fmaxf(mx0, __shfl_xor_sync(0xffffffffu, mx0, 2));
        mx1 = fmaxf(mx1, __shfl_xor_sync(0xffffffffu, mx1, 1));
        mx1 = fmaxf(mx1, __shfl_xor_sync(0xffffffffu, mx1, 2));

        float mn0 = fmaxf(m0, mx0), mn1 = fmaxf(m1, mx1);
        float cr0 = __expf(m0 - mn0), cr1 = __expf(m1 - mn1);
        m0 = mn0; m1 = mn1;

        float s0 = 0.0f, s1 = 0.0f;
        #pragma unroll
        for (int ni = 0; ni < 8; ++ni) {
            sc[ni][0] = __expf(sc[ni][0] - mn0); s0 += sc[ni][0];
            sc[ni][1] = __expf(sc[ni][1] - mn0); s0 += sc[ni][1];
            sc[ni][2] = __expf(sc[ni][2] - mn1); s1 += sc[ni][2];
            sc[ni][3] = __expf(sc[ni][3] - mn1); s1 += sc[ni][3];
        }
        s0 += __shfl_xor_sync(0xffffffffu, s0, 1);
        s0 += __shfl_xor_sync(0xffffffffu, s0, 2);
        s1 += __shfl_xor_sync(0xffffffffu, s1, 1);
        s1 += __shfl_xor_sync(0xffffffffu, s1, 2);
        l0 = l0 * cr0 + s0;
        l1 = l1 * cr1 + s1;

        #pragma unroll
        for (int ni = 0; ni < 8; ++ni) {
            int cb = (ni * 8 + tg * 2) * PSTR;
            Psm[cb        + warp_m + g    ] = to_tf32(sc[ni][0]);
            Psm[cb + PSTR + warp_m + g    ] = to_tf32(sc[ni][1]);
            Psm[cb        + warp_m + g + 8] = to_tf32(sc[ni][2]);
            Psm[cb + PSTR + warp_m + g + 8] = to_tf32(sc[ni][3]);
        }
        __syncwarp();

        #pragma unroll
        for (int ni = 0; ni < 8; ++ni) {
            o[ni][0] *= cr0; o[ni][1] *= cr0;
            o[ni][2] *= cr1; o[ni][3] *= cr1;
        }

        #pragma unroll
        for (int ks = 0; ks < 8; ++ks) {
            uint32_t pa0 = __float_as_uint(Psm[(ks * 8 + tg    ) * PSTR + warp_m + g    ]);
            uint32_t pa1 = __float_as_uint(Psm[(ks * 8 + tg    ) * PSTR + warp_m + g + 8]);
            uint32_t pa2 = __float_as_uint(Psm[(ks * 8 + tg + 4) * PSTR + warp_m + g    ]);
            uint32_t pa3 = __float_as_uint(Psm[(ks * 8 + tg + 4) * PSTR + warp_m + g + 8]);
            #pragma unroll
            for (int ni = 0; ni < 8; ++ni) {
                uint32_t b0 = __float_as_uint(Vsm[(ks * 8 + tg    ) * KSTR + ni * 8 + g]);
                uint32_t b1 = __float_as_uint(Vsm[(ks * 8 + tg + 4) * KSTR + ni * 8 + g]);
                mma_tf32(o[ni][0], o[ni][1], o[ni][2], o[ni][3],
                         pa0, pa1, pa2, pa3, b0, b1);
            }
        }
    }

    float inv0 = 1.0f / l0, inv1 = 1.0f / l1;
    const int row0 = q0 + warp_m + g;
    #pragma unroll
    for (int ni = 0; ni < 8; ++ni) {
        int col = ni * 8 + tg * 2;
        *(float2*)&Og[((size_t)row0 * NH + h) * HD + col] =
            make_float2(o[ni][0] * inv0, o[ni][1] * inv0);
        *(float2*)&Og[((size_t)(row0 + 8) * NH + h) * HD + col] =
            make_float2(o[ni][2] * inv1, o[ni][3] * inv1);
    }
}

// ---------------------------------------------------------------------------
// Launch: fused QKV (RoPE in epilogue) -> attention -> output projection
// ---------------------------------------------------------------------------
extern "C" void kernel_launch(void* const* d_in, const int* in_sizes, int n_in,
                              void* d_out, int out_size)
{
    const float* x  = (const float*)d_in[0];
    const float* wq = (const float*)d_in[2];
    const float* wk = (const float*)d_in[3];
    const float* wv = (const float*)d_in[4];
    const float* wo = (const float*)d_in[5];
    float* out = (float*)d_out;

    float *q, *k, *v, *a;
    cudaGetSymbolAddress((void**)&q, g_q);
    cudaGetSymbolAddress((void**)&k, g_k);
    cudaGetSymbolAddress((void**)&v, g_v);
    cudaGetSymbolAddress((void**)&a, g_attn);

    cudaFuncSetAttribute(attn_mma_kernel,
                         cudaFuncAttributeMaxDynamicSharedMemorySize, ASMEM);

    qkv_gemm_kernel<<<dim3(24, 16), 256>>>(x, wq, wk, wv, q, k, v);
    attn_mma_kernel<<<dim3(S_LEN / AQT, NH), 256, ASMEM>>>(q, k, v, a);
    out_gemm_kernel<<<dim3(16, 16), 256>>>(a, wo, out);
}

// round 6
// speedup vs baseline: 4.6431x; 1.2600x over previous
#include <cuda_runtime.h>
#include <cuda_fp16.h>
#include <math.h>
#include <stdint.h>

#define S_LEN  2048
#define HIDDEN 2048
#define NH     32
#define NKV    8
#define HD     64

// Scratch (device globals — no allocation allowed in kernel_launch)
__device__ float g_q[S_LEN * NH * HD];      // [s, h, d]
__device__ float g_k[S_LEN * NKV * HD];     // [s, kvh, d]
__device__ float g_v[S_LEN * NKV * HD];     // [s, kvh, d]
__device__ float g_attn[S_LEN * NH * HD];   // [s, h*64+d]

// log2(500000)/32
#define L2T_OVER_32 0.5916115177913804f

// ---------------------------------------------------------------------------
// Helpers
// ---------------------------------------------------------------------------
__device__ __forceinline__ uint32_t h2pack(float lo, float hi) {
    __half2 t = __floats2half2_rn(lo, hi);   // x = lo (low 16 bits)
    return *(uint32_t*)&t;
}

// fp16 mma m16n8k16, fp32 accumulate
__device__ __forceinline__ void mma_fp16(
    float& c0, float& c1, float& c2, float& c3,
    uint32_t a0, uint32_t a1, uint32_t a2, uint32_t a3,
    uint32_t b0, uint32_t b1)
{
    asm volatile(
        "mma.sync.aligned.m16n8k16.row.col.f32.f16.f16.f32 "
        "{%0,%1,%2,%3},{%4,%5,%6,%7},{%8,%9},{%0,%1,%2,%3};"
        : "+f"(c0), "+f"(c1), "+f"(c2), "+f"(c3)
        : "r"(a0), "r"(a1), "r"(a2), "r"(a3), "r"(b0), "r"(b1));
}

// ---------------------------------------------------------------------------
// FP16 GEMM core: C[.,N] 128x128 tile = A[2048,2048] @ B[2048,N], fp32 I/O.
// BK=32, 256 threads (8 warps 4x2), warp tile 32x64, m16n8k16.
// Smem: packed half2 words, [row][16 words]; word slot for k-pair p is
// (p&3)*4 + (p>>2), 16B-unit XOR-swizzled by (row>>1)&3. One LDS.128 per row
// yields fragments for BOTH k16 chunks. Double-buffered.
// ---------------------------------------------------------------------------
#define GNT (HIDDEN / 32)   // 64 k-tiles

__device__ __forceinline__ void gemm_fp16_core(
    const float* __restrict__ A, const float* __restrict__ B,
    float* __restrict__ C, int N, int bm, int bn, int rope,
    uint32_t* sAB)   // 8192 words: A stages [0,2048), B stages [4096,6144)
{
    const int tid  = threadIdx.x;
    const int lane = tid & 31;
    const int wid  = tid >> 5;
    const int g    = lane >> 2;
    const int tg   = lane & 3;
    const int warp_m = (wid >> 1) * 32;
    const int warp_n = (wid & 1) * 64;

    // Producer mappings
    const int arow = tid >> 1;           // 0..127
    const int ak0  = (tid & 1) * 16;     // 0 or 16 (k offset)
    const int bnl  = tid & 127;          // 0..127 (n)
    const int bk0  = (tid >> 7) * 16;    // 0 or 16

    const float* Ap = A + (size_t)(bm + arow) * HIDDEN + ak0;
    const float* Bp = B + (size_t)bk0 * N + bn + bnl;

    const int swzA  = (arow >> 1) & 3;
    const int swzB  = (bnl  >> 1) & 3;
    const int aoffw = (ak0 >> 4) * 2;    // 0 or 2 words
    const int boffw = (bk0 >> 4) * 2;

    float acc[2][8][4];
    #pragma unroll
    for (int mi = 0; mi < 2; ++mi)
        #pragma unroll
        for (int ni = 0; ni < 8; ++ni)
            #pragma unroll
            for (int c = 0; c < 4; ++c) acc[mi][ni][c] = 0.0f;

    uint32_t pa[8], pb[8];
    // ---- load + pack tile 0 ----
    {
        float4 a0 = *(const float4*)(Ap);
        float4 a1 = *(const float4*)(Ap + 4);
        float4 a2 = *(const float4*)(Ap + 8);
        float4 a3 = *(const float4*)(Ap + 12);
        pa[0] = h2pack(a0.x, a0.y); pa[1] = h2pack(a0.z, a0.w);
        pa[2] = h2pack(a1.x, a1.y); pa[3] = h2pack(a1.z, a1.w);
        pa[4] = h2pack(a2.x, a2.y); pa[5] = h2pack(a2.z, a2.w);
        pa[6] = h2pack(a3.x, a3.y); pa[7] = h2pack(a3.z, a3.w);
        #pragma unroll
        for (int j = 0; j < 8; ++j) {
            float b0 = Bp[(size_t)(2 * j) * N];
            float b1 = Bp[(size_t)(2 * j + 1) * N];
            pb[j] = h2pack(b0, b1);
        }
    }
    {
        uint32_t* As = sAB;
        uint32_t* Bs = sAB + 4096;
        #pragma unroll
        for (int j = 0; j < 4; ++j)
            *(uint2*)&As[arow * 16 + 4 * (j ^ swzA) + aoffw] = make_uint2(pa[j], pa[j + 4]);
        #pragma unroll
        for (int j = 0; j < 4; ++j)
            *(uint2*)&Bs[bnl * 16 + 4 * (j ^ swzB) + boffw] = make_uint2(pb[j], pb[j + 4]);
    }
    __syncthreads();

    for (int t = 0; t < GNT; ++t) {
        const int cur = t & 1;

        // ---- prefetch tile t+1 ----
        if (t + 1 < GNT) {
            const float* ap = Ap + (t + 1) * 32;
            float4 a0 = *(const float4*)(ap);
            float4 a1 = *(const float4*)(ap + 4);
            float4 a2 = *(const float4*)(ap + 8);
            float4 a3 = *(const float4*)(ap + 12);
            pa[0] = h2pack(a0.x, a0.y); pa[1] = h2pack(a0.z, a0.w);
            pa[2] = h2pack(a1.x, a1.y); pa[3] = h2pack(a1.z, a1.w);
            pa[4] = h2pack(a2.x, a2.y); pa[5] = h2pack(a2.z, a2.w);
            pa[6] = h2pack(a3.x, a3.y); pa[7] = h2pack(a3.z, a3.w);
            const float* bp = Bp + (size_t)(t + 1) * 32 * N;
            #pragma unroll
            for (int j = 0; j < 8; ++j) {
                float b0 = bp[(size_t)(2 * j) * N];
                float b1 = bp[(size_t)(2 * j + 1) * N];
                pb[j] = h2pack(b0, b1);
            }
        }

        // ---- mma on stage cur ----
        const uint32_t* As = sAB + cur * 2048;
        const uint32_t* Bs = sAB + 4096 + cur * 2048;

        uint4 va[2], vb[2];
        #pragma unroll
        for (int mi = 0; mi < 2; ++mi) {
            int r0 = warp_m + mi * 16 + g;
            int r1 = r0 + 8;
            va[mi] = *(const uint4*)&As[r0 * 16 + 4 * (tg ^ ((r0 >> 1) & 3))];
            vb[mi] = *(const uint4*)&As[r1 * 16 + 4 * (tg ^ ((r1 >> 1) & 3))];
        }
        #pragma unroll
        for (int ni = 0; ni < 8; ++ni) {
            int rn = warp_n + ni * 8 + g;
            uint4 bv = *(const uint4*)&Bs[rn * 16 + 4 * (tg ^ ((rn >> 1) & 3))];
            #pragma unroll
            for (int mi = 0; mi < 2; ++mi) {
                mma_fp16(acc[mi][ni][0], acc[mi][ni][1],
                         acc[mi][ni][2], acc[mi][ni][3],
                         va[mi].x, vb[mi].x, va[mi].y, vb[mi].y,
                         bv.x, bv.y);
                mma_fp16(acc[mi][ni][0], acc[mi][ni][1],
                         acc[mi][ni][2], acc[mi][ni][3],
                         va[mi].z, vb[mi].z, va[mi].w, vb[mi].w,
                         bv.z, bv.w);
            }
        }

        __syncthreads();
        if (t + 1 < GNT) {
            uint32_t* nA = sAB + ((t + 1) & 1) * 2048;
            uint32_t* nB = sAB + 4096 + ((t + 1) & 1) * 2048;
            #pragma unroll
            for (int j = 0; j < 4; ++j)
                *(uint2*)&nA[arow * 16 + 4 * (j ^ swzA) + aoffw] = make_uint2(pa[j], pa[j + 4]);
            #pragma unroll
            for (int j = 0; j < 4; ++j)
                *(uint2*)&nB[bnl * 16 + 4 * (j ^ swzB) + boffw] = make_uint2(pb[j], pb[j + 4]);
        }
        __syncthreads();
    }

    // ---- epilogue (fused RoPE) ----
    #pragma unroll
    for (int mi = 0; mi < 2; ++mi) {
        #pragma unroll
        for (int ni = 0; ni < 8; ++ni) {
            int row = bm + warp_m + mi * 16 + g;
            int col = bn + warp_n + ni * 8 + tg * 2;
            float c0 = acc[mi][ni][0], c1 = acc[mi][ni][1];
            float c2 = acc[mi][ni][2], c3 = acc[mi][ni][3];
            if (rope) {
                int i = (col & 63) >> 1;
                float freq = exp2f(-(float)i * L2T_OVER_32);
                float sn0, cs0, sn1, cs1;
                sincosf((float)row * freq, &sn0, &cs0);
                sincosf((float)(row + 8) * freq, &sn1, &cs1);
                float r0 = c0 * cs0 - c1 * sn0;
                float r1 = c0 * sn0 + c1 * cs0;
                float r2 = c2 * cs1 - c3 * sn1;
                float r3 = c2 * sn1 + c3 * cs1;
                c0 = r0; c1 = r1; c2 = r2; c3 = r3;
            }
            *(float2*)&C[(size_t)row * N + col]       = make_float2(c0, c1);
            *(float2*)&C[(size_t)(row + 8) * N + col] = make_float2(c2, c3);
        }
    }
}

// Fused QKV projection: blockIdx.x 0..23 selects matrix + column tile.
__global__ __launch_bounds__(256) void qkv_gemm_kernel(
    const float* __restrict__ x,
    const float* __restrict__ wq, const float* __restrict__ wk,
    const float* __restrict__ wv,
    float* __restrict__ q, float* __restrict__ k, float* __restrict__ v)
{
    __shared__ uint32_t sAB[8192];
    const int bx = blockIdx.x;
    const float* B; float* C; int N, bn, rope;
    if (bx < 16)      { B = wq; C = q; N = NH * HD;  bn = bx * 128;        rope = 1; }
    else if (bx < 20) { B = wk; C = k; N = NKV * HD; bn = (bx - 16) * 128; rope = 1; }
    else              { B = wv; C = v; N = NKV * HD; bn = (bx - 20) * 128; rope = 0; }
    gemm_fp16_core(x, B, C, N, blockIdx.y * 128, bn, rope, sAB);
}

__global__ __launch_bounds__(256) void out_gemm_kernel(
    const float* __restrict__ a, const float* __restrict__ w,
    float* __restrict__ out)
{
    __shared__ uint32_t sAB[8192];
    gemm_fp16_core(a, w, out, HIDDEN, blockIdx.y * 128, blockIdx.x * 128, 0, sAB);
}

// ---------------------------------------------------------------------------
// Causal GQA flash attention, fp16 m16n8k16.
// Block: 128 q-rows x 1 head, 8 warps (16 rows each), 64-key tiles.
// Packed half2 smem:
//   K2[dp][key]  : halves = dims (2dp, 2dp+1) of a key      (scores B-frags)
//   V2[kp][dim]  : halves = keys (2kp, 2kp+1) at a dim      (PV B-frags)
//   P2[pair][row]: Q staging (dim pairs) then P (key pairs) (A-frags)
// ---------------------------------------------------------------------------
#define AQT   128
#define AKT   64
#define KSTR2 72     // 72 % 32 == 8 -> conflict-free frag loads
#define PSTR2 136    // 136 % 32 == 8

__global__ __launch_bounds__(256) void attn_mma_kernel(
    const float* __restrict__ Qg, const float* __restrict__ Kg,
    const float* __restrict__ Vg, float* __restrict__ Og)
{
    __shared__ uint32_t K2[32 * KSTR2];
    __shared__ uint32_t V2[32 * KSTR2];
    __shared__ uint32_t P2[32 * PSTR2];

    const int h    = blockIdx.y;
    const int kvh  = h >> 2;
    const int qt   = gridDim.x - 1 - blockIdx.x;   // heavy tiles first
    const int q0   = qt * AQT;
    const int tid  = threadIdx.x;
    const int lane = tid & 31;
    const int wid  = tid >> 5;
    const int g    = lane >> 2;
    const int tg   = lane & 3;
    const int warp_m = wid * 16;

    // ---- stage Q (scaled 1/8) as dim-pair half2, transposed ----
    {
        int r  = tid >> 1;
        int cb = (tid & 1) * 32;
        const float* src = Qg + ((size_t)(q0 + r) * NH + h) * HD + cb;
        #pragma unroll
        for (int j = 0; j < 32; j += 4) {
            float4 t = *(const float4*)(src + j);
            P2[((cb + j) >> 1) * PSTR2 + r]       = h2pack(t.x * 0.125f, t.y * 0.125f);
            P2[(((cb + j) >> 1) + 1) * PSTR2 + r] = h2pack(t.z * 0.125f, t.w * 0.125f);
        }
    }
    __syncthreads();

    uint32_t qf[4][4];
    #pragma unroll
    for (int ks = 0; ks < 4; ++ks) {
        qf[ks][0] = P2[(8 * ks + tg)     * PSTR2 + warp_m + g];
        qf[ks][1] = P2[(8 * ks + tg)     * PSTR2 + warp_m + g + 8];
        qf[ks][2] = P2[(8 * ks + tg + 4) * PSTR2 + warp_m + g];
        qf[ks][3] = P2[(8 * ks + tg + 4) * PSTR2 + warp_m + g + 8];
    }

    float m0 = -INFINITY, m1 = -INFINITY, l0 = 0.0f, l1 = 0.0f;
    float o[8][4];
    #pragma unroll
    for (int ni = 0; ni < 8; ++ni)
        #pragma unroll
        for (int c = 0; c < 4; ++c) o[ni][c] = 0.0f;

    const int ntiles = (q0 + AQT) / AKT;
    for (int t = 0; t < ntiles; ++t) {
        const int kt = t * AKT;
        __syncthreads();
        // ---- stage K (dim-pair packed) ----
        {
            int r  = tid >> 2;            // key 0..63
            int cb = (tid & 3) * 16;      // dims
            const float* ks = Kg + ((size_t)(kt + r) * NKV + kvh) * HD + cb;
            #pragma unroll
            for (int j = 0; j < 16; j += 4) {
                float4 a = *(const float4*)(ks + j);
                K2[((cb + j) >> 1) * KSTR2 + r]       = h2pack(a.x, a.y);
                K2[(((cb + j) >> 1) + 1) * KSTR2 + r] = h2pack(a.z, a.w);
            }
        }
        // ---- stage V (key-pair packed) ----
        {
            int kp = tid >> 3;            // 0..31
            int d0 = (tid & 7) * 8;       // dims
            const float* ve = Vg + ((size_t)(kt + 2 * kp) * NKV + kvh) * HD + d0;
            const float* vo = Vg + ((size_t)(kt + 2 * kp + 1) * NKV + kvh) * HD + d0;
            float4 e0 = *(const float4*)(ve);
            float4 e1 = *(const float4*)(ve + 4);
            float4 o0 = *(const float4*)(vo);
            float4 o1 = *(const float4*)(vo + 4);
            uint4 w0 = make_uint4(h2pack(e0.x, o0.x), h2pack(e0.y, o0.y),
                                  h2pack(e0.z, o0.z), h2pack(e0.w, o0.w));
            uint4 w1 = make_uint4(h2pack(e1.x, o1.x), h2pack(e1.y, o1.y),
                                  h2pack(e1.z, o1.z), h2pack(e1.w, o1.w));
            *(uint4*)&V2[kp * KSTR2 + d0]     = w0;
            *(uint4*)&V2[kp * KSTR2 + d0 + 4] = w1;
        }
        __syncthreads();

        // ---- S = Q @ K^T ----
        float sc[8][4];
        #pragma unroll
        for (int ni = 0; ni < 8; ++ni) {
            sc[ni][0] = sc[ni][1] = sc[ni][2] = sc[ni][3] = 0.0f;
            #pragma unroll
            for (int ks = 0; ks < 4; ++ks) {
                uint32_t b0 = K2[(8 * ks + tg)     * KSTR2 + ni * 8 + g];
                uint32_t b1 = K2[(8 * ks + tg + 4) * KSTR2 + ni * 8 + g];
                mma_fp16(sc[ni][0], sc[ni][1], sc[ni][2], sc[ni][3],
                         qf[ks][0], qf[ks][1], qf[ks][2], qf[ks][3], b0, b1);
            }
        }

        // ---- causal mask ----
        const int row0 = q0 + warp_m + g;
        const int row1 = row0 + 8;
        if (kt + AKT - 1 > q0 + warp_m) {
            #pragma unroll
            for (int ni = 0; ni < 8; ++ni) {
                int col = kt + ni * 8 + tg * 2;
                if (col     > row0) sc[ni][0] = -INFINITY;
                if (col + 1 > row0) sc[ni][1] = -INFINITY;
                if (col     > row1) sc[ni][2] = -INFINITY;
                if (col + 1 > row1) sc[ni][3] = -INFINITY;
            }
        }

        // ---- online softmax ----
        float mx0 = -INFINITY, mx1 = -INFINITY;
        #pragma unroll
        for (int ni = 0; ni < 8; ++ni) {
            mx0 = fmaxf(mx0, fmaxf(sc[ni][0], sc[ni][1]));
            mx1 = fmaxf(mx1, fmaxf(sc[ni][2], sc[ni][3]));
        }
        mx0 = fmaxf(mx0, __shfl_xor_sync(0xffffffffu, mx0, 1));
        mx0 = fmaxf(mx0, __shfl_xor_sync(0xffffffffu, mx0, 2));
        mx1 = fmaxf(mx1, __shfl_xor_sync(0xffffffffu, mx1, 1));
        mx1 = fmaxf(mx1, __shfl_xor_sync(0xffffffffu, mx1, 2));

        float mn0 = fmaxf(m0, mx0), mn1 = fmaxf(m1, mx1);
        float cr0 = __expf(m0 - mn0), cr1 = __expf(m1 - mn1);
        m0 = mn0; m1 = mn1;

        float s0 = 0.0f, s1 = 0.0f;
        #pragma unroll
        for (int ni = 0; ni < 8; ++ni) {
            sc[ni][0] = __expf(sc[ni][0] - mn0); s0 += sc[ni][0];
            sc[ni][1] = __expf(sc[ni][1] - mn0); s0 += sc[ni][1];
            sc[ni][2] = __expf(sc[ni][2] - mn1); s1 += sc[ni][2];
            sc[ni][3] = __expf(sc[ni][3] - mn1); s1 += sc[ni][3];
        }
        s0 += __shfl_xor_sync(0xffffffffu, s0, 1);
        s0 += __shfl_xor_sync(0xffffffffu, s0, 2);
        s1 += __shfl_xor_sync(0xffffffffu, s1, 1);
        s1 += __shfl_xor_sync(0xffffffffu, s1, 2);
        l0 = l0 * cr0 + s0;
        l1 = l1 * cr1 + s1;

        // ---- store P^T (key-pair packed), warp-private columns ----
        #pragma unroll
        for (int ni = 0; ni < 8; ++ni) {
            int kp = ni * 4 + tg;
            P2[kp * PSTR2 + warp_m + g]     = h2pack(sc[ni][0], sc[ni][1]);
            P2[kp * PSTR2 + warp_m + g + 8] = h2pack(sc[ni][2], sc[ni][3]);
        }
        __syncwarp();

        // ---- rescale O ----
        #pragma unroll
        for (int ni = 0; ni < 8; ++ni) {
            o[ni][0] *= cr0; o[ni][1] *= cr0;
            o[ni][2] *= cr1; o[ni][3] *= cr1;
        }

        // ---- O += P @ V ----
        #pragma unroll
        for (int ks = 0; ks < 4; ++ks) {
            uint32_t pa0 = P2[(8 * ks + tg)     * PSTR2 + warp_m + g];
            uint32_t pa1 = P2[(8 * ks + tg)     * PSTR2 + warp_m + g + 8];
            uint32_t pa2 = P2[(8 * ks + tg + 4) * PSTR2 + warp_m + g];
            uint32_t pa3 = P2[(8 * ks + tg + 4) * PSTR2 + warp_m + g + 8];
            #pragma unroll
            for (int ni = 0; ni < 8; ++ni) {
                uint32_t b0 = V2[(8 * ks + tg)     * KSTR2 + ni * 8 + g];
                uint32_t b1 = V2[(8 * ks + tg + 4) * KSTR2 + ni * 8 + g];
                mma_fp16(o[ni][0], o[ni][1], o[ni][2], o[ni][3],
                         pa0, pa1, pa2, pa3, b0, b1);
            }
        }
    }

    // ---- normalize and write ----
    float inv0 = 1.0f / l0, inv1 = 1.0f / l1;
    const int row0 = q0 + warp_m + g;
    #pragma unroll
    for (int ni = 0; ni < 8; ++ni) {
        int col = ni * 8 + tg * 2;
        *(float2*)&Og[((size_t)row0 * NH + h) * HD + col] =
            make_float2(o[ni][0] * inv0, o[ni][1] * inv0);
        *(float2*)&Og[((size_t)(row0 + 8) * NH + h) * HD + col] =
            make_float2(o[ni][2] * inv1, o[ni][3] * inv1);
    }
}

// ---------------------------------------------------------------------------
// Launch: fused QKV (RoPE in epilogue) -> attention -> output projection
// ---------------------------------------------------------------------------
extern "C" void kernel_launch(void* const* d_in, const int* in_sizes, int n_in,
                              void* d_out, int out_size)
{
    const float* x  = (const float*)d_in[0];
    const float* wq = (const float*)d_in[2];
    const float* wk = (const float*)d_in[3];
    const float* wv = (const float*)d_in[4];
    const float* wo = (const float*)d_in[5];
    float* out = (float*)d_out;

    float *q, *k, *v, *a;
    cudaGetSymbolAddress((void**)&q, g_q);
    cudaGetSymbolAddress((void**)&k, g_k);
    cudaGetSymbolAddress((void**)&v, g_v);
    cudaGetSymbolAddress((void**)&a, g_attn);

    qkv_gemm_kernel<<<dim3(24, 16), 256>>>(x, wq, wk, wv, q, k, v);
    attn_mma_kernel<<<dim3(S_LEN / AQT, NH), 256>>>(q, k, v, a);
    out_gemm_kernel<<<dim3(16, 16), 256>>>(a, wo, out);
}

// round 7
// speedup vs baseline: 7.6710x; 1.6521x over previous
#include <cuda_runtime.h>
#include <cuda_fp16.h>
#include <math.h>
#include <stdint.h>

#define S_LEN  2048
#define HIDDEN 2048
#define NH     32
#define NKV    8
#define HD     64

// ---------------------------------------------------------------------------
// Device scratch (half data stored as packed uint32 words = half2)
// Interleaved "image" layout for GEMM operands, per row of 1024 words:
//   word (t*16 + 4j + i)  holds k-pair p = 16t + j + 4i  (halves k=2p,2p+1)
// ---------------------------------------------------------------------------
__device__ uint32_t g_xI  [2048 * 1024];  // x image        [m][k]
__device__ uint32_t g_wqI [2048 * 1024];  // wq^T image     [n][k]
__device__ uint32_t g_wkI [ 512 * 1024];  // wk^T image
__device__ uint32_t g_wvI [ 512 * 1024];  // wv^T image
__device__ uint32_t g_woI [2048 * 1024];  // wo^T image
__device__ uint32_t g_attnI[2048 * 1024]; // attention out image [s][k]
__device__ uint32_t g_qh  [2048 * 1024];  // q half  [s][NH*32 wordpairs]
__device__ uint32_t g_kh  [2048 * 256];   // k half  [s][NKV*32]
__device__ uint32_t g_vh  [2048 * 256];   // v half  [s][NKV*32]

// log2(500000)/32
#define L2T_OVER_32 0.5916115177913804f

__device__ __forceinline__ uint32_t h2pack(float lo, float hi) {
    __half2 t = __floats2half2_rn(lo, hi);
    return *(uint32_t*)&t;
}

__device__ __forceinline__ uint32_t smem_u32(const void* p) {
    uint32_t a;
    asm("{ .reg .u64 t; cvta.to.shared.u64 t, %1; cvt.u32.u64 %0, t; }"
        : "=r"(a) : "l"(p));
    return a;
}

__device__ __forceinline__ void mma_fp16(
    float& c0, float& c1, float& c2, float& c3,
    uint32_t a0, uint32_t a1, uint32_t a2, uint32_t a3,
    uint32_t b0, uint32_t b1)
{
    asm volatile(
        "mma.sync.aligned.m16n8k16.row.col.f32.f16.f16.f32 "
        "{%0,%1,%2,%3},{%4,%5,%6,%7},{%8,%9},{%0,%1,%2,%3};"
        : "+f"(c0), "+f"(c1), "+f"(c2), "+f"(c3)
        : "r"(a0), "r"(a1), "r"(a2), "r"(a3), "r"(b0), "r"(b1));
}

#define CP16(dst, src) \
    asm volatile("cp.async.cg.shared.global [%0], [%1], 16;" \
                 :: "r"(dst), "l"(src) : "memory")
#define CP_COMMIT() asm volatile("cp.async.commit_group;" ::: "memory")
#define CP_WAIT(n)  asm volatile("cp.async.wait_group %0;" :: "n"(n) : "memory")

// ---------------------------------------------------------------------------
// Conversion kernels
// ---------------------------------------------------------------------------
// Row-major fp32 [rows][2048] -> interleaved half image [rows][1024 words]
__global__ __launch_bounds__(256) void conv_rm_kernel(
    const float* __restrict__ src, uint32_t* __restrict__ dst)
{
    int idx = blockIdx.x * 256 + threadIdx.x;
    int row = idx >> 10, w = idx & 1023;
    int t = w >> 4, j = (w >> 2) & 3, i = w & 3;
    int p = 16 * t + j + 4 * i;
    float2 f = *(const float2*)(src + (size_t)row * 2048 + 2 * p);
    dst[idx] = h2pack(f.x, f.y);
}

// fp32 w[2048 k][N n] -> transposed interleaved half image [n][1024 words]
__global__ __launch_bounds__(256) void conv_T_kernel(
    const float* __restrict__ w, uint32_t* __restrict__ dst, int N)
{
    __shared__ float sm[32][33];
    const int k0 = blockIdx.y * 32, n0 = blockIdx.x * 32;
    const int tid = threadIdx.x;
    {
        int lk = tid >> 3, ln = (tid & 7) * 4;
        float4 v = *(const float4*)(w + (size_t)(k0 + lk) * N + n0 + ln);
        sm[lk][ln] = v.x; sm[lk][ln + 1] = v.y;
        sm[lk][ln + 2] = v.z; sm[lk][ln + 3] = v.w;
    }
    __syncthreads();
    if (tid < 128) {
        int n = tid >> 2, j = tid & 3;
        uint32_t wd[4];
        #pragma unroll
        for (int i = 0; i < 4; ++i) {
            int kk = 2 * j + 8 * i;
            wd[i] = h2pack(sm[kk][n], sm[kk + 1][n]);
        }
        *(uint4*)&dst[(size_t)(n0 + n) * 1024 + (k0 >> 5) * 16 + 4 * j] =
            make_uint4(wd[0], wd[1], wd[2], wd[3]);
    }
}

// ---------------------------------------------------------------------------
// FP16 GEMM core on interleaved images. 128x128 tile, BK=32, 256 thr,
// warp tile 32x64, m16n8k16, 3-stage cp.async pipeline.
// OUTHALF=1: write half2 words (with optional rope + scale); else fp32.
// ---------------------------------------------------------------------------
#define GNT (HIDDEN / 32)   // 64 k-tiles

template<int OUTHALF>
__device__ __forceinline__ void gemm_half_core(
    const uint32_t* __restrict__ Aimg, const uint32_t* __restrict__ Bimg,
    void* Cout, int N, int bm, int bn, int rope, float oscale,
    uint32_t* sAB)
{
    const uint32_t sbase = smem_u32(sAB);
    const int tid  = threadIdx.x;
    const int lane = tid & 31;
    const int wid  = tid >> 5;
    const int g    = lane >> 2;
    const int tg   = lane & 3;
    const int warp_m = (wid >> 1) * 32;
    const int warp_n = (wid & 1) * 64;

    // Producer mapping (rows 0..127 for both A and B, 2 chunks each)
    const int prow = tid >> 1;
    const int pj0  = (tid & 1) * 2;
    const int swzP = (prow >> 1) & 3;
    const uint32_t d0 = (uint32_t)(prow * 16 + 4 * (pj0 ^ swzP)) * 4;
    const uint32_t d1 = (uint32_t)(prow * 16 + 4 * ((pj0 + 1) ^ swzP)) * 4;
    const uint32_t* srcA = Aimg + (size_t)(bm + prow) * 1024 + 4 * pj0;
    const uint32_t* srcB = Bimg + (size_t)(bn + prow) * 1024 + 4 * pj0;

    float acc[2][8][4];
    #pragma unroll
    for (int mi = 0; mi < 2; ++mi)
        #pragma unroll
        for (int ni = 0; ni < 8; ++ni)
            #pragma unroll
            for (int c = 0; c < 4; ++c) acc[mi][ni][c] = 0.0f;

#define G_ISSUE(t) do { \
    uint32_t _ab = sbase + ((t) % 3) * 16384; \
    const uint32_t* _sa = srcA + (size_t)(t) * 16; \
    const uint32_t* _sb = srcB + (size_t)(t) * 16; \
    CP16(_ab + d0, _sa); \
    CP16(_ab + d1, _sa + 4); \
    CP16(_ab + 8192 + d0, _sb); \
    CP16(_ab + 8192 + d1, _sb + 4); \
    CP_COMMIT(); \
} while (0)

    G_ISSUE(0);
    G_ISSUE(1);

    for (int t = 0; t < GNT; ++t) {
        if (t < GNT - 1) { CP_WAIT(1); } else { CP_WAIT(0); }
        __syncthreads();
        if (t + 2 < GNT) G_ISSUE(t + 2);

        const uint32_t* As = sAB + (t % 3) * 4096;
        const uint32_t* Bs = As + 2048;

        uint4 va[2], vb[2];
        #pragma unroll
        for (int mi = 0; mi < 2; ++mi) {
            int r0 = warp_m + mi * 16 + g;
            int r1 = r0 + 8;
            va[mi] = *(const uint4*)&As[r0 * 16 + 4 * (tg ^ ((r0 >> 1) & 3))];
            vb[mi] = *(const uint4*)&As[r1 * 16 + 4 * (tg ^ ((r1 >> 1) & 3))];
        }
        #pragma unroll
        for (int ni = 0; ni < 8; ++ni) {
            int rn = warp_n + ni * 8 + g;
            uint4 bv = *(const uint4*)&Bs[rn * 16 + 4 * (tg ^ ((rn >> 1) & 3))];
            #pragma unroll
            for (int mi = 0; mi < 2; ++mi) {
                mma_fp16(acc[mi][ni][0], acc[mi][ni][1],
                         acc[mi][ni][2], acc[mi][ni][3],
                         va[mi].x, vb[mi].x, va[mi].y, vb[mi].y, bv.x, bv.y);
                mma_fp16(acc[mi][ni][0], acc[mi][ni][1],
                         acc[mi][ni][2], acc[mi][ni][3],
                         va[mi].z, vb[mi].z, va[mi].w, vb[mi].w, bv.z, bv.w);
            }
        }
    }
#undef G_ISSUE

    // ---- epilogue ----
    #pragma unroll
    for (int mi = 0; mi < 2; ++mi) {
        #pragma unroll
        for (int ni = 0; ni < 8; ++ni) {
            int row = bm + warp_m + mi * 16 + g;
            int col = bn + warp_n + ni * 8 + tg * 2;
            float c0 = acc[mi][ni][0] * oscale, c1 = acc[mi][ni][1] * oscale;
            float c2 = acc[mi][ni][2] * oscale, c3 = acc[mi][ni][3] * oscale;
            if (rope) {
                int i = (col & 63) >> 1;
                float freq = exp2f(-(float)i * L2T_OVER_32);
                float sn0, cs0, sn1, cs1;
                sincosf((float)row * freq, &sn0, &cs0);
                sincosf((float)(row + 8) * freq, &sn1, &cs1);
                float r0 = c0 * cs0 - c1 * sn0;
                float r1 = c0 * sn0 + c1 * cs0;
                float r2 = c2 * cs1 - c3 * sn1;
                float r3 = c2 * sn1 + c3 * cs1;
                c0 = r0; c1 = r1; c2 = r2; c3 = r3;
            }
            if (OUTHALF) {
                uint32_t* Ch = (uint32_t*)Cout;
                Ch[(size_t)row * (N >> 1) + (col >> 1)]       = h2pack(c0, c1);
                Ch[(size_t)(row + 8) * (N >> 1) + (col >> 1)] = h2pack(c2, c3);
            } else {
                float* Cf = (float*)Cout;
                *(float2*)&Cf[(size_t)row * N + col]       = make_float2(c0, c1);
                *(float2*)&Cf[(size_t)(row + 8) * N + col] = make_float2(c2, c3);
            }
        }
    }
}

// Fused QKV projection: blockIdx.x 0..23 selects matrix + column tile.
__global__ __launch_bounds__(256, 2) void qkv_gemm_kernel(
    uint32_t* __restrict__ qh, uint32_t* __restrict__ kh,
    uint32_t* __restrict__ vh)
{
    __shared__ __align__(16) uint32_t sAB[12288];
    const int bx = blockIdx.x;
    const uint32_t* B; uint32_t* C; int N, bn, rope; float sc;
    if (bx < 16)      { B = g_wqI; C = qh; N = NH * HD;  bn = bx * 128;        rope = 1; sc = 0.125f; }
    else if (bx < 20) { B = g_wkI; C = kh; N = NKV * HD; bn = (bx - 16) * 128; rope = 1; sc = 1.0f; }
    else              { B = g_wvI; C = vh; N = NKV * HD; bn = (bx - 20) * 128; rope = 0; sc = 1.0f; }
    gemm_half_core<1>(g_xI, B, C, N, blockIdx.y * 128, bn, rope, sc, sAB);
}

__global__ __launch_bounds__(256, 2) void out_gemm_kernel(float* __restrict__ out)
{
    __shared__ __align__(16) uint32_t sAB[12288];
    gemm_half_core<0>(g_attnI, g_woI, out, HIDDEN,
                      blockIdx.y * 128, blockIdx.x * 128, 0, 1.0f, sAB);
}

// ---------------------------------------------------------------------------
// Causal GQA flash attention, fp16 m16n8k16, half inputs/outputs.
// Block: 128 q-rows x 1 head, 8 warps, 64-key tiles.
//   K2[dp][key]  halves = dims (2dp,2dp+1)   (score B-frags)
//   V2[kp][dim]  halves = keys (2kp,2kp+1)   (PV B-frags)
//   P2[pair][row] Q staging then P           (A-frags)
// ---------------------------------------------------------------------------
#define AQT   128
#define AKT   64
#define KSTR2 72
#define PSTR2 136

__global__ __launch_bounds__(256) void attn_mma_kernel(
    const uint32_t* __restrict__ Qh, const uint32_t* __restrict__ Kh,
    const uint32_t* __restrict__ Vh, uint32_t* __restrict__ OutI)
{
    __shared__ uint32_t K2[32 * KSTR2];
    __shared__ uint32_t V2[32 * KSTR2];
    __shared__ uint32_t P2[32 * PSTR2];

    const int h    = blockIdx.y;
    const int kvh  = h >> 2;
    const int qt   = gridDim.x - 1 - blockIdx.x;   // heavy tiles first
    const int q0   = qt * AQT;
    const int tid  = threadIdx.x;
    const int lane = tid & 31;
    const int wid  = tid >> 5;
    const int g    = lane >> 2;
    const int tg   = lane & 3;
    const int warp_m = wid * 16;

    // ---- stage Q (pre-scaled) transposed into P2 ----
    {
        int r  = tid >> 1;
        int cb = (tid & 1) * 16;     // dp offset
        const uint32_t* src = Qh + (size_t)(q0 + r) * 1024 + h * 32 + cb;
        #pragma unroll
        for (int w4 = 0; w4 < 16; w4 += 4) {
            uint4 t = *(const uint4*)(src + w4);
            P2[(cb + w4 + 0) * PSTR2 + r] = t.x;
            P2[(cb + w4 + 1) * PSTR2 + r] = t.y;
            P2[(cb + w4 + 2) * PSTR2 + r] = t.z;
            P2[(cb + w4 + 3) * PSTR2 + r] = t.w;
        }
    }
    __syncthreads();

    uint32_t qf[4][4];
    #pragma unroll
    for (int ks = 0; ks < 4; ++ks) {
        qf[ks][0] = P2[(8 * ks + tg)     * PSTR2 + warp_m + g];
        qf[ks][1] = P2[(8 * ks + tg)     * PSTR2 + warp_m + g + 8];
        qf[ks][2] = P2[(8 * ks + tg + 4) * PSTR2 + warp_m + g];
        qf[ks][3] = P2[(8 * ks + tg + 4) * PSTR2 + warp_m + g + 8];
    }

    float m0 = -INFINITY, m1 = -INFINITY, l0 = 0.0f, l1 = 0.0f;
    float o[8][4];
    #pragma unroll
    for (int ni = 0; ni < 8; ++ni)
        #pragma unroll
        for (int c = 0; c < 4; ++c) o[ni][c] = 0.0f;

    const int ntiles = (q0 + AQT) / AKT;
    for (int t = 0; t < ntiles; ++t) {
        const int kt = t * AKT;
        __syncthreads();
        // ---- stage K ----
        {
            int key = tid >> 2;
            int cb  = (tid & 3) * 8;
            const uint32_t* src = Kh + (size_t)(kt + key) * 256 + kvh * 32 + cb;
            uint4 t0 = *(const uint4*)(src);
            uint4 t1 = *(const uint4*)(src + 4);
            K2[(cb + 0) * KSTR2 + key] = t0.x;
            K2[(cb + 1) * KSTR2 + key] = t0.y;
            K2[(cb + 2) * KSTR2 + key] = t0.z;
            K2[(cb + 3) * KSTR2 + key] = t0.w;
            K2[(cb + 4) * KSTR2 + key] = t1.x;
            K2[(cb + 5) * KSTR2 + key] = t1.y;
            K2[(cb + 6) * KSTR2 + key] = t1.z;
            K2[(cb + 7) * KSTR2 + key] = t1.w;
        }
        // ---- stage V (key-pair packed via byte_perm) ----
        {
            int kp = tid >> 3;
            int d8 = (tid & 7) * 4;   // dp units
            const uint32_t* ve = Vh + (size_t)(kt + 2 * kp) * 256 + kvh * 32 + d8;
            const uint32_t* vo = Vh + (size_t)(kt + 2 * kp + 1) * 256 + kvh * 32 + d8;
            uint4 a = *(const uint4*)ve;
            uint4 b = *(const uint4*)vo;
            uint32_t* dst = &V2[kp * KSTR2 + 2 * d8];
            dst[0] = __byte_perm(a.x, b.x, 0x5410);
            dst[1] = __byte_perm(a.x, b.x, 0x7632);
            dst[2] = __byte_perm(a.y, b.y, 0x5410);
            dst[3] = __byte_perm(a.y, b.y, 0x7632);
            dst[4] = __byte_perm(a.z, b.z, 0x5410);
            dst[5] = __byte_perm(a.z, b.z, 0x7632);
            dst[6] = __byte_perm(a.w, b.w, 0x5410);
            dst[7] = __byte_perm(a.w, b.w, 0x7632);
        }
        __syncthreads();

        // ---- S = Q @ K^T ----
        float sc[8][4];
        #pragma unroll
        for (int ni = 0; ni < 8; ++ni) {
            sc[ni][0] = sc[ni][1] = sc[ni][2] = sc[ni][3] = 0.0f;
            #pragma unroll
            for (int ks = 0; ks < 4; ++ks) {
                uint32_t b0 = K2[(8 * ks + tg)     * KSTR2 + ni * 8 + g];
                uint32_t b1 = K2[(8 * ks + tg + 4) * KSTR2 + ni * 8 + g];
                mma_fp16(sc[ni][0], sc[ni][1], sc[ni][2], sc[ni][3],
                         qf[ks][0], qf[ks][1], qf[ks][2], qf[ks][3], b0, b1);
            }
        }

        // ---- causal mask ----
        const int row0 = q0 + warp_m + g;
        const int row1 = row0 + 8;
        if (kt + AKT - 1 > q0 + warp_m) {
            #pragma unroll
            for (int ni = 0; ni < 8; ++ni) {
                int col = kt + ni * 8 + tg * 2;
                if (col     > row0) sc[ni][0] = -INFINITY;
                if (col + 1 > row0) sc[ni][1] = -INFINITY;
                if (col     > row1) sc[ni][2] = -INFINITY;
                if (col + 1 > row1) sc[ni][3] = -INFINITY;
            }
        }

        // ---- online softmax ----
        float mx0 = -INFINITY, mx1 = -INFINITY;
        #pragma unroll
        for (int ni = 0; ni < 8; ++ni) {
            mx0 = fmaxf(mx0, fmaxf(sc[ni][0], sc[ni][1]));
            mx1 = fmaxf(mx1, fmaxf(sc[ni][2], sc[ni][3]));
        }
        mx0 = fmaxf(mx0, __shfl_xor_sync(0xffffffffu, mx0, 1));
        mx0 = fmaxf(mx0, __shfl_xor_sync(0xffffffffu, mx0, 2));
        mx1 = fmaxf(mx1, __shfl_xor_sync(0xffffffffu, mx1, 1));
        mx1 = fmaxf(mx1, __shfl_xor_sync(0xffffffffu, mx1, 2));

        float mn0 = fmaxf(m0, mx0), mn1 = fmaxf(m1, mx1);
        float cr0 = __expf(m0 - mn0), cr1 = __expf(m1 - mn1);
        m0 = mn0; m1 = mn1;

        float s0 = 0.0f, s1 = 0.0f;
        #pragma unroll
        for (int ni = 0; ni < 8; ++ni) {
            sc[ni][0] = __expf(sc[ni][0] - mn0); s0 += sc[ni][0];
            sc[ni][1] = __expf(sc[ni][1] - mn0); s0 += sc[ni][1];
            sc[ni][2] = __expf(sc[ni][2] - mn1); s1 += sc[ni][2];
            sc[ni][3] = __expf(sc[ni][3] - mn1); s1 += sc[ni][3];
        }
        s0 += __shfl_xor_sync(0xffffffffu, s0, 1);
        s0 += __shfl_xor_sync(0xffffffffu, s0, 2);
        s1 += __shfl_xor_sync(0xffffffffu, s1, 1);
        s1 += __shfl_xor_sync(0xffffffffu, s1, 2);
        l0 = l0 * cr0 + s0;
        l1 = l1 * cr1 + s1;

        // ---- store P^T (key-pair packed), warp-private columns ----
        #pragma unroll
        for (int ni = 0; ni < 8; ++ni) {
            int kp = ni * 4 + tg;
            P2[kp * PSTR2 + warp_m + g]     = h2pack(sc[ni][0], sc[ni][1]);
            P2[kp * PSTR2 + warp_m + g + 8] = h2pack(sc[ni][2], sc[ni][3]);
        }
        __syncwarp();

        // ---- rescale O ----
        #pragma unroll
        for (int ni = 0; ni < 8; ++ni) {
            o[ni][0] *= cr0; o[ni][1] *= cr0;
            o[ni][2] *= cr1; o[ni][3] *= cr1;
        }

        // ---- O += P @ V ----
        #pragma unroll
        for (int ks = 0; ks < 4; ++ks) {
            uint32_t pa0 = P2[(8 * ks + tg)     * PSTR2 + warp_m + g];
            uint32_t pa1 = P2[(8 * ks + tg)     * PSTR2 + warp_m + g + 8];
            uint32_t pa2 = P2[(8 * ks + tg + 4) * PSTR2 + warp_m + g];
            uint32_t pa3 = P2[(8 * ks + tg + 4) * PSTR2 + warp_m + g + 8];
            #pragma unroll
            for (int ni = 0; ni < 8; ++ni) {
                uint32_t b0 = V2[(8 * ks + tg)     * KSTR2 + ni * 8 + g];
                uint32_t b1 = V2[(8 * ks + tg + 4) * KSTR2 + ni * 8 + g];
                mma_fp16(o[ni][0], o[ni][1], o[ni][2], o[ni][3],
                         pa0, pa1, pa2, pa3, b0, b1);
            }
        }
    }

    // ---- normalize and write to interleaved image ----
    float inv0 = 1.0f / l0, inv1 = 1.0f / l1;
    const int row0 = q0 + warp_m + g;
    #pragma unroll
    for (int ni = 0; ni < 8; ++ni) {
        int p  = h * 32 + ni * 4 + tg;       // global k-pair index
        int pl = p & 15;
        int w  = (p >> 4) * 16 + 4 * (pl & 3) + (pl >> 2);
        OutI[(size_t)row0 * 1024 + w]       = h2pack(o[ni][0] * inv0, o[ni][1] * inv0);
        OutI[(size_t)(row0 + 8) * 1024 + w] = h2pack(o[ni][2] * inv1, o[ni][3] * inv1);
    }
}

// ---------------------------------------------------------------------------
// Launch: conversions -> fused QKV -> attention -> output projection
// ---------------------------------------------------------------------------
extern "C" void kernel_launch(void* const* d_in, const int* in_sizes, int n_in,
                              void* d_out, int out_size)
{
    const float* x  = (const float*)d_in[0];
    const float* wq = (const float*)d_in[2];
    const float* wk = (const float*)d_in[3];
    const float* wv = (const float*)d_in[4];
    const float* wo = (const float*)d_in[5];
    float* out = (float*)d_out;

    uint32_t *xI, *wqI, *wkI, *wvI, *woI, *attnI, *qh, *kh, *vh;
    cudaGetSymbolAddress((void**)&xI, g_xI);
    cudaGetSymbolAddress((void**)&wqI, g_wqI);
    cudaGetSymbolAddress((void**)&wkI, g_wkI);
    cudaGetSymbolAddress((void**)&wvI, g_wvI);
    cudaGetSymbolAddress((void**)&woI, g_woI);
    cudaGetSymbolAddress((void**)&attnI, g_attnI);
    cudaGetSymbolAddress((void**)&qh, g_qh);
    cudaGetSymbolAddress((void**)&kh, g_kh);
    cudaGetSymbolAddress((void**)&vh, g_vh);

    conv_rm_kernel<<<8192, 256>>>(x, xI);
    conv_T_kernel<<<dim3(64, 64), 256>>>(wq, wqI, 2048);
    conv_T_kernel<<<dim3(16, 64), 256>>>(wk, wkI, 512);
    conv_T_kernel<<<dim3(16, 64), 256>>>(wv, wvI, 512);
    conv_T_kernel<<<dim3(64, 64), 256>>>(wo, woI, 2048);

    qkv_gemm_kernel<<<dim3(24, 16), 256>>>(qh, kh, vh);
    attn_mma_kernel<<<dim3(S_LEN / AQT, NH), 256>>>(qh, kh, vh, attnI);
    out_gemm_kernel<<<dim3(16, 16), 256>>>(out);
}

// round 8
// speedup vs baseline: 7.9350x; 1.0344x over previous
#include <cuda_runtime.h>
#include <cuda_fp16.h>
#include <math.h>
#include <stdint.h>

#define S_LEN  2048
#define HIDDEN 2048
#define NH     32
#define NKV    8
#define HD     64

// ---------------------------------------------------------------------------
// Device scratch (half data as packed uint32 = half2)
// GEMM "image" layout per row of 1024 words:
//   word (t*16 + 4j + i) holds k-pair p = 16t + j + 4i (halves k=2p,2p+1)
// Q/K transposed images: [head*32 + dimpair][seq] words.
// ---------------------------------------------------------------------------
__device__ uint32_t g_xI   [2048 * 1024];  // x image        [m][k]
__device__ uint32_t g_wqI  [2048 * 1024];  // wq^T image     [n][k]
__device__ uint32_t g_wkI  [ 512 * 1024];  // wk^T image
__device__ uint32_t g_wvI  [ 512 * 1024];  // wv^T image
__device__ uint32_t g_woI  [2048 * 1024];  // wo^T image
__device__ uint32_t g_attnI[2048 * 1024];  // attention out image [s][k]
__device__ uint32_t g_qimg [1024 * 2048];  // q^T image [h*32+dp][s] (pre-scaled)
__device__ uint32_t g_kimg [ 256 * 2048];  // k^T image [kvh*32+dp][s]
__device__ uint32_t g_vh   [2048 * 256];   // v half [s][kvh*32+dp]

// log2(500000)/32
#define L2T_OVER_32 0.5916115177913804f

__device__ __forceinline__ uint32_t h2pack(float lo, float hi) {
    __half2 t = __floats2half2_rn(lo, hi);
    return *(uint32_t*)&t;
}

__device__ __forceinline__ uint32_t smem_u32(const void* p) {
    uint32_t a;
    asm("{ .reg .u64 t; cvta.to.shared.u64 t, %1; cvt.u32.u64 %0, t; }"
        : "=r"(a) : "l"(p));
    return a;
}

__device__ __forceinline__ void mma_fp16(
    float& c0, float& c1, float& c2, float& c3,
    uint32_t a0, uint32_t a1, uint32_t a2, uint32_t a3,
    uint32_t b0, uint32_t b1)
{
    asm volatile(
        "mma.sync.aligned.m16n8k16.row.col.f32.f16.f16.f32 "
        "{%0,%1,%2,%3},{%4,%5,%6,%7},{%8,%9},{%0,%1,%2,%3};"
        : "+f"(c0), "+f"(c1), "+f"(c2), "+f"(c3)
        : "r"(a0), "r"(a1), "r"(a2), "r"(a3), "r"(b0), "r"(b1));
}

#define CP16(dst, src) \
    asm volatile("cp.async.cg.shared.global [%0], [%1], 16;" \
                 :: "r"(dst), "l"(src) : "memory")
#define CP_COMMIT() asm volatile("cp.async.commit_group;" ::: "memory")
#define CP_WAIT(n)  asm volatile("cp.async.wait_group %0;" :: "n"(n) : "memory")

// ---------------------------------------------------------------------------
// Conversion kernels
// ---------------------------------------------------------------------------
__global__ __launch_bounds__(256) void conv_rm_kernel(
    const float* __restrict__ src, uint32_t* __restrict__ dst)
{
    int idx = blockIdx.x * 256 + threadIdx.x;
    int row = idx >> 10, w = idx & 1023;
    int t = w >> 4, j = (w >> 2) & 3, i = w & 3;
    int p = 16 * t + j + 4 * i;
    float2 f = *(const float2*)(src + (size_t)row * 2048 + 2 * p);
    dst[idx] = h2pack(f.x, f.y);
}

__global__ __launch_bounds__(256) void conv_T_kernel(
    const float* __restrict__ w, uint32_t* __restrict__ dst, int N)
{
    __shared__ float sm[32][33];
    const int k0 = blockIdx.y * 32, n0 = blockIdx.x * 32;
    const int tid = threadIdx.x;
    {
        int lk = tid >> 3, ln = (tid & 7) * 4;
        float4 v = *(const float4*)(w + (size_t)(k0 + lk) * N + n0 + ln);
        sm[lk][ln] = v.x; sm[lk][ln + 1] = v.y;
        sm[lk][ln + 2] = v.z; sm[lk][ln + 3] = v.w;
    }
    __syncthreads();
    if (tid < 128) {
        int n = tid >> 2, j = tid & 3;
        uint32_t wd[4];
        #pragma unroll
        for (int i = 0; i < 4; ++i) {
            int kk = 2 * j + 8 * i;
            wd[i] = h2pack(sm[kk][n], sm[kk + 1][n]);
        }
        *(uint4*)&dst[(size_t)(n0 + n) * 1024 + (k0 >> 5) * 16 + 4 * j] =
            make_uint4(wd[0], wd[1], wd[2], wd[3]);
    }
}

// ---------------------------------------------------------------------------
// FP16 GEMM core (unchanged mainloop from round 7). Epilogue modes:
//   0: fp32 row-major   1: q image (scale 1/8 + rope)
//   2: k image (rope)   3: v half rows
// ---------------------------------------------------------------------------
#define GNT (HIDDEN / 32)

__device__ __forceinline__ void gemm_half_core(
    const uint32_t* __restrict__ Aimg, const uint32_t* __restrict__ Bimg,
    void* Cout, int N, int bm, int bn, int mode, uint32_t* sAB)
{
    const uint32_t sbase = smem_u32(sAB);
    const int tid  = threadIdx.x;
    const int lane = tid & 31;
    const int wid  = tid >> 5;
    const int g    = lane >> 2;
    const int tg   = lane & 3;
    const int warp_m = (wid >> 1) * 32;
    const int warp_n = (wid & 1) * 64;

    const int prow = tid >> 1;
    const int pj0  = (tid & 1) * 2;
    const int swzP = (prow >> 1) & 3;
    const uint32_t d0 = (uint32_t)(prow * 16 + 4 * (pj0 ^ swzP)) * 4;
    const uint32_t d1 = (uint32_t)(prow * 16 + 4 * ((pj0 + 1) ^ swzP)) * 4;
    const uint32_t* srcA = Aimg + (size_t)(bm + prow) * 1024 + 4 * pj0;
    const uint32_t* srcB = Bimg + (size_t)(bn + prow) * 1024 + 4 * pj0;

    float acc[2][8][4];
    #pragma unroll
    for (int mi = 0; mi < 2; ++mi)
        #pragma unroll
        for (int ni = 0; ni < 8; ++ni)
            #pragma unroll
            for (int c = 0; c < 4; ++c) acc[mi][ni][c] = 0.0f;

#define G_ISSUE(t) do { \
    uint32_t _ab = sbase + ((t) % 3) * 16384; \
    const uint32_t* _sa = srcA + (size_t)(t) * 16; \
    const uint32_t* _sb = srcB + (size_t)(t) * 16; \
    CP16(_ab + d0, _sa); \
    CP16(_ab + d1, _sa + 4); \
    CP16(_ab + 8192 + d0, _sb); \
    CP16(_ab + 8192 + d1, _sb + 4); \
    CP_COMMIT(); \
} while (0)

    G_ISSUE(0);
    G_ISSUE(1);

    for (int t = 0; t < GNT; ++t) {
        if (t < GNT - 1) { CP_WAIT(1); } else { CP_WAIT(0); }
        __syncthreads();
        if (t + 2 < GNT) G_ISSUE(t + 2);

        const uint32_t* As = sAB + (t % 3) * 4096;
        const uint32_t* Bs = As + 2048;

        uint4 va[2], vb[2];
        #pragma unroll
        for (int mi = 0; mi < 2; ++mi) {
            int r0 = warp_m + mi * 16 + g;
            int r1 = r0 + 8;
            va[mi] = *(const uint4*)&As[r0 * 16 + 4 * (tg ^ ((r0 >> 1) & 3))];
            vb[mi] = *(const uint4*)&As[r1 * 16 + 4 * (tg ^ ((r1 >> 1) & 3))];
        }
        #pragma unroll
        for (int ni = 0; ni < 8; ++ni) {
            int rn = warp_n + ni * 8 + g;
            uint4 bv = *(const uint4*)&Bs[rn * 16 + 4 * (tg ^ ((rn >> 1) & 3))];
            #pragma unroll
            for (int mi = 0; mi < 2; ++mi) {
                mma_fp16(acc[mi][ni][0], acc[mi][ni][1],
                         acc[mi][ni][2], acc[mi][ni][3],
                         va[mi].x, vb[mi].x, va[mi].y, vb[mi].y, bv.x, bv.y);
                mma_fp16(acc[mi][ni][0], acc[mi][ni][1],
                         acc[mi][ni][2], acc[mi][ni][3],
                         va[mi].z, vb[mi].z, va[mi].w, vb[mi].w, bv.z, bv.w);
            }
        }
    }
#undef G_ISSUE

    #pragma unroll
    for (int mi = 0; mi < 2; ++mi) {
        #pragma unroll
        for (int ni = 0; ni < 8; ++ni) {
            int row = bm + warp_m + mi * 16 + g;
            int col = bn + warp_n + ni * 8 + tg * 2;
            float c0 = acc[mi][ni][0], c1 = acc[mi][ni][1];
            float c2 = acc[mi][ni][2], c3 = acc[mi][ni][3];
            if (mode == 1) { c0 *= 0.125f; c1 *= 0.125f; c2 *= 0.125f; c3 *= 0.125f; }
            if (mode == 1 || mode == 2) {
                int i = (col & 63) >> 1;
                float freq = exp2f(-(float)i * L2T_OVER_32);
                float sn0, cs0, sn1, cs1;
                sincosf((float)row * freq, &sn0, &cs0);
                sincosf((float)(row + 8) * freq, &sn1, &cs1);
                float r0 = c0 * cs0 - c1 * sn0;
                float r1 = c0 * sn0 + c1 * cs0;
                float r2 = c2 * cs1 - c3 * sn1;
                float r3 = c2 * sn1 + c3 * cs1;
                c0 = r0; c1 = r1; c2 = r2; c3 = r3;
                // transposed dim-pair image store
                uint32_t* img = (uint32_t*)Cout;
                int hh = col >> 6;
                int dp = (col & 63) >> 1;
                img[(size_t)(hh * 32 + dp) * 2048 + row]     = h2pack(c0, c1);
                img[(size_t)(hh * 32 + dp) * 2048 + row + 8] = h2pack(c2, c3);
            } else if (mode == 3) {
                uint32_t* vh = (uint32_t*)Cout;
                vh[(size_t)row * 256 + (col >> 1)]       = h2pack(c0, c1);
                vh[(size_t)(row + 8) * 256 + (col >> 1)] = h2pack(c2, c3);
            } else {
                float* Cf = (float*)Cout;
                *(float2*)&Cf[(size_t)row * N + col]       = make_float2(c0, c1);
                *(float2*)&Cf[(size_t)(row + 8) * N + col] = make_float2(c2, c3);
            }
        }
    }
}

__global__ __launch_bounds__(256, 2) void qkv_gemm_kernel(
    uint32_t* __restrict__ qimg, uint32_t* __restrict__ kimg,
    uint32_t* __restrict__ vh)
{
    __shared__ __align__(16) uint32_t sAB[12288];
    const int bx = blockIdx.x;
    const uint32_t* B; void* C; int N, bn, mode;
    if (bx < 16)      { B = g_wqI; C = qimg; N = NH * HD;  bn = bx * 128;        mode = 1; }
    else if (bx < 20) { B = g_wkI; C = kimg; N = NKV * HD; bn = (bx - 16) * 128; mode = 2; }
    else              { B = g_wvI; C = vh;   N = NKV * HD; bn = (bx - 20) * 128; mode = 3; }
    gemm_half_core(g_xI, B, C, N, blockIdx.y * 128, bn, mode, sAB);
}

__global__ __launch_bounds__(256, 2) void out_gemm_kernel(float* __restrict__ out)
{
    __shared__ __align__(16) uint32_t sAB[12288];
    gemm_half_core(g_attnI, g_woI, out, HIDDEN,
                   blockIdx.y * 128, blockIdx.x * 128, 0, sAB);
}

// ---------------------------------------------------------------------------
// Causal GQA flash attention, fp16 m16n8k16.
// Q/K staged via cp.async from pre-transposed images; K/V double-buffered.
// Dynamic smem (words): K2[2][32*72] | V2[2][32*72] | P2[32*136]
// ---------------------------------------------------------------------------
#define AQT   128
#define AKT   64
#define KSTR2 72
#define PSTR2 136
#define KBUF  (32 * KSTR2)              // 2304 words per buffer
#define ASMEM2 ((4 * KBUF + 32 * PSTR2) * 4)   // 54272 bytes

__global__ __launch_bounds__(256) void attn_mma_kernel(
    const uint32_t* __restrict__ Qimg, const uint32_t* __restrict__ Kimg,
    const uint32_t* __restrict__ Vh, uint32_t* __restrict__ OutI)
{
    extern __shared__ uint32_t dsm[];
    uint32_t* K2 = dsm;                 // 2 buffers
    uint32_t* V2 = dsm + 2 * KBUF;      // 2 buffers
    uint32_t* P2 = dsm + 4 * KBUF;
    const uint32_t K2b = smem_u32(K2);
    const uint32_t P2b = smem_u32(P2);

    const int h    = blockIdx.y;
    const int kvh  = h >> 2;
    const int qt   = gridDim.x - 1 - blockIdx.x;   // heavy tiles first
    const int q0   = qt * AQT;
    const int tid  = threadIdx.x;
    const int lane = tid & 31;
    const int wid  = tid >> 5;
    const int g    = lane >> 2;
    const int tg   = lane & 3;
    const int warp_m = wid * 16;

    // ---- prologue: Q stage + K(0) via cp.async, V(0) via LDG/perm ----
    {
        int dp = tid >> 3, seg = (tid & 7) * 16;
        const uint32_t* src = Qimg + (size_t)(h * 32 + dp) * 2048 + q0 + seg;
        uint32_t dst = P2b + (uint32_t)(dp * PSTR2 + seg) * 4;
        CP16(dst, src); CP16(dst + 16, src + 4);
        CP16(dst + 32, src + 8); CP16(dst + 48, src + 12);
    }
    {
        int dp = tid >> 3, seg = (tid & 7) * 8;
        const uint32_t* src = Kimg + (size_t)(kvh * 32 + dp) * 2048 + seg;
        uint32_t dst = K2b + (uint32_t)(dp * KSTR2 + seg) * 4;
        CP16(dst, src); CP16(dst + 16, src + 4);
    }
    CP_COMMIT();
    {
        int kp = tid >> 3, d8 = (tid & 7) * 4;
        const uint32_t* ve = Vh + (size_t)(2 * kp) * 256 + kvh * 32 + d8;
        const uint32_t* vo = Vh + (size_t)(2 * kp + 1) * 256 + kvh * 32 + d8;
        uint4 a = *(const uint4*)ve;
        uint4 b = *(const uint4*)vo;
        uint32_t* dst = &V2[kp * KSTR2 + 2 * d8];
        dst[0] = __byte_perm(a.x, b.x, 0x5410);
        dst[1] = __byte_perm(a.x, b.x, 0x7632);
        dst[2] = __byte_perm(a.y, b.y, 0x5410);
        dst[3] = __byte_perm(a.y, b.y, 0x7632);
        dst[4] = __byte_perm(a.z, b.z, 0x5410);
        dst[5] = __byte_perm(a.z, b.z, 0x7632);
        dst[6] = __byte_perm(a.w, b.w, 0x5410);
        dst[7] = __byte_perm(a.w, b.w, 0x7632);
    }
    CP_WAIT(0);
    __syncthreads();

    // Q A-fragments
    uint32_t qf[4][4];
    #pragma unroll
    for (int ks = 0; ks < 4; ++ks) {
        qf[ks][0] = P2[(8 * ks + tg)     * PSTR2 + warp_m + g];
        qf[ks][1] = P2[(8 * ks + tg)     * PSTR2 + warp_m + g + 8];
        qf[ks][2] = P2[(8 * ks + tg + 4) * PSTR2 + warp_m + g];
        qf[ks][3] = P2[(8 * ks + tg + 4) * PSTR2 + warp_m + g + 8];
    }

    float m0 = -INFINITY, m1 = -INFINITY, l0 = 0.0f, l1 = 0.0f;
    float o[8][4];
    #pragma unroll
    for (int ni = 0; ni < 8; ++ni)
        #pragma unroll
        for (int c = 0; c < 4; ++c) o[ni][c] = 0.0f;

    const int ntiles = (q0 + AQT) / AKT;
    for (int t = 0; t < ntiles; ++t) {
        const int cur = t & 1;
        const int nxt = cur ^ 1;
        const int kt  = t * AKT;
        if (t > 0) { CP_WAIT(0); __syncthreads(); }

        const bool havenext = (t + 1 < ntiles);
        uint4 va_, vb_;
        if (havenext) {
            const int ktn = kt + AKT;
            int dp = tid >> 3, seg = (tid & 7) * 8;
            const uint32_t* src = Kimg + (size_t)(kvh * 32 + dp) * 2048 + ktn + seg;
            uint32_t dst = K2b + (uint32_t)(nxt * KBUF + dp * KSTR2 + seg) * 4;
            CP16(dst, src); CP16(dst + 16, src + 4);
            CP_COMMIT();
            int kp = tid >> 3, d8 = (tid & 7) * 4;
            va_ = *(const uint4*)(Vh + (size_t)(ktn + 2 * kp) * 256 + kvh * 32 + d8);
            vb_ = *(const uint4*)(Vh + (size_t)(ktn + 2 * kp + 1) * 256 + kvh * 32 + d8);
        }

        // ---- S = Q @ K^T on K2[cur] ----
        const uint32_t* Kc = K2 + cur * KBUF;
        float sc[8][4];
        #pragma unroll
        for (int ni = 0; ni < 8; ++ni) {
            sc[ni][0] = sc[ni][1] = sc[ni][2] = sc[ni][3] = 0.0f;
            #pragma unroll
            for (int ks = 0; ks < 4; ++ks) {
                uint32_t b0 = Kc[(8 * ks + tg)     * KSTR2 + ni * 8 + g];
                uint32_t b1 = Kc[(8 * ks + tg + 4) * KSTR2 + ni * 8 + g];
                mma_fp16(sc[ni][0], sc[ni][1], sc[ni][2], sc[ni][3],
                         qf[ks][0], qf[ks][1], qf[ks][2], qf[ks][3], b0, b1);
            }
        }

        // ---- V(t+1) perm + STS (LDG latency hidden under score mma) ----
        if (havenext) {
            int kp = tid >> 3, d8 = (tid & 7) * 4;
            uint32_t* dst = &V2[nxt * KBUF + kp * KSTR2 + 2 * d8];
            dst[0] = __byte_perm(va_.x, vb_.x, 0x5410);
            dst[1] = __byte_perm(va_.x, vb_.x, 0x7632);
            dst[2] = __byte_perm(va_.y, vb_.y, 0x5410);
            dst[3] = __byte_perm(va_.y, vb_.y, 0x7632);
            dst[4] = __byte_perm(va_.z, vb_.z, 0x5410);
            dst[5] = __byte_perm(va_.z, vb_.z, 0x7632);
            dst[6] = __byte_perm(va_.w, vb_.w, 0x5410);
            dst[7] = __byte_perm(va_.w, vb_.w, 0x7632);
        }

        // ---- causal mask ----
        const int row0 = q0 + warp_m + g;
        const int row1 = row0 + 8;
        if (kt + AKT - 1 > q0 + warp_m) {
            #pragma unroll
            for (int ni = 0; ni < 8; ++ni) {
                int col = kt + ni * 8 + tg * 2;
                if (col     > row0) sc[ni][0] = -INFINITY;
                if (col + 1 > row0) sc[ni][1] = -INFINITY;
                if (col     > row1) sc[ni][2] = -INFINITY;
                if (col + 1 > row1) sc[ni][3] = -INFINITY;
            }
        }

        // ---- online softmax ----
        float mx0 = -INFINITY, mx1 = -INFINITY;
        #pragma unroll
        for (int ni = 0; ni < 8; ++ni) {
            mx0 = fmaxf(mx0, fmaxf(sc[ni][0], sc[ni][1]));
            mx1 = fmaxf(mx1, fmaxf(sc[ni][2], sc[ni][3]));
        }
        mx0 = fmaxf(mx0, __shfl_xor_sync(0xffffffffu, mx0, 1));
        mx0 = fmaxf(mx0, __shfl_xor_sync(0xffffffffu, mx0, 2));
        mx1 = fmaxf(mx1, __shfl_xor_sync(0xffffffffu, mx1, 1));
        mx1 = fmaxf(mx1, __shfl_xor_sync(0xffffffffu, mx1, 2));

        float mn0 = fmaxf(m0, mx0), mn1 = fmaxf(m1, mx1);
        float cr0 = __expf(m0 - mn0), cr1 = __expf(m1 - mn1);
        m0 = mn0; m1 = mn1;

        float s0 = 0.0f, s1 = 0.0f;
        #pragma unroll
        for (int ni = 0; ni < 8; ++ni) {
            sc[ni][0] = __expf(sc[ni][0] - mn0); s0 += sc[ni][0];
            sc[ni][1] = __expf(sc[ni][1] - mn0); s0 += sc[ni][1];
            sc[ni][2] = __expf(sc[ni][2] - mn1); s1 += sc[ni][2];
            sc[ni][3] = __expf(sc[ni][3] - mn1); s1 += sc[ni][3];
        }
        s0 += __shfl_xor_sync(0xffffffffu, s0, 1);
        s0 += __shfl_xor_sync(0xffffffffu, s0, 2);
        s1 += __shfl_xor_sync(0xffffffffu, s1, 1);
        s1 += __shfl_xor_sync(0xffffffffu, s1, 2);
        l0 = l0 * cr0 + s0;
        l1 = l1 * cr1 + s1;

        // ---- store P^T (warp-private columns) ----
        #pragma unroll
        for (int ni = 0; ni < 8; ++ni) {
            int kp = ni * 4 + tg;
            P2[kp * PSTR2 + warp_m + g]     = h2pack(sc[ni][0], sc[ni][1]);
            P2[kp * PSTR2 + warp_m + g + 8] = h2pack(sc[ni][2], sc[ni][3]);
        }
        __syncwarp();

        // ---- rescale O ----
        #pragma unroll
        for (int ni = 0; ni < 8; ++ni) {
            o[ni][0] *= cr0; o[ni][1] *= cr0;
            o[ni][2] *= cr1; o[ni][3] *= cr1;
        }

        // ---- O += P @ V on V2[cur] ----
        const uint32_t* Vc = V2 + cur * KBUF;
        #pragma unroll
        for (int ks = 0; ks < 4; ++ks) {
            uint32_t pa0 = P2[(8 * ks + tg)     * PSTR2 + warp_m + g];
            uint32_t pa1 = P2[(8 * ks + tg)     * PSTR2 + warp_m + g + 8];
            uint32_t pa2 = P2[(8 * ks + tg + 4) * PSTR2 + warp_m + g];
            uint32_t pa3 = P2[(8 * ks + tg + 4) * PSTR2 + warp_m + g + 8];
            #pragma unroll
            for (int ni = 0; ni < 8; ++ni) {
                uint32_t b0 = Vc[(8 * ks + tg)     * KSTR2 + ni * 8 + g];
                uint32_t b1 = Vc[(8 * ks + tg + 4) * KSTR2 + ni * 8 + g];
                mma_fp16(o[ni][0], o[ni][1], o[ni][2], o[ni][3],
                         pa0, pa1, pa2, pa3, b0, b1);
            }
        }
    }

    // ---- normalize and write interleaved image ----
    float inv0 = 1.0f / l0, inv1 = 1.0f / l1;
    const int row0 = q0 + warp_m + g;
    #pragma unroll
    for (int ni = 0; ni < 8; ++ni) {
        int p  = h * 32 + ni * 4 + tg;
        int pl = p & 15;
        int w  = (p >> 4) * 16 + 4 * (pl & 3) + (pl >> 2);
        OutI[(size_t)row0 * 1024 + w]       = h2pack(o[ni][0] * inv0, o[ni][1] * inv0);
        OutI[(size_t)(row0 + 8) * 1024 + w] = h2pack(o[ni][2] * inv1, o[ni][3] * inv1);
    }
}

// ---------------------------------------------------------------------------
// Launch
// ---------------------------------------------------------------------------
extern "C" void kernel_launch(void* const* d_in, const int* in_sizes, int n_in,
                              void* d_out, int out_size)
{
    const float* x  = (const float*)d_in[0];
    const float* wq = (const float*)d_in[2];
    const float* wk = (const float*)d_in[3];
    const float* wv = (const float*)d_in[4];
    const float* wo = (const float*)d_in[5];
    float* out = (float*)d_out;

    uint32_t *xI, *wqI, *wkI, *wvI, *woI, *attnI, *qimg, *kimg, *vh;
    cudaGetSymbolAddress((void**)&xI, g_xI);
    cudaGetSymbolAddress((void**)&wqI, g_wqI);
    cudaGetSymbolAddress((void**)&wkI, g_wkI);
    cudaGetSymbolAddress((void**)&wvI, g_wvI);
    cudaGetSymbolAddress((void**)&woI, g_woI);
    cudaGetSymbolAddress((void**)&attnI, g_attnI);
    cudaGetSymbolAddress((void**)&qimg, g_qimg);
    cudaGetSymbolAddress((void**)&kimg, g_kimg);
    cudaGetSymbolAddress((void**)&vh, g_vh);

    cudaFuncSetAttribute(attn_mma_kernel,
                         cudaFuncAttributeMaxDynamicSharedMemorySize, ASMEM2);

    conv_rm_kernel<<<8192, 256>>>(x, xI);
    conv_T_kernel<<<dim3(64, 64), 256>>>(wq, wqI, 2048);
    conv_T_kernel<<<dim3(16, 64), 256>>>(wk, wkI, 512);
    conv_T_kernel<<<dim3(16, 64), 256>>>(wv, wvI, 512);
    conv_T_kernel<<<dim3(64, 64), 256>>>(wo, woI, 2048);

    qkv_gemm_kernel<<<dim3(24, 16), 256>>>(qimg, kimg, vh);
    attn_mma_kernel<<<dim3(S_LEN / AQT, NH), 256, ASMEM2>>>(qimg, kimg, vh, attnI);
    out_gemm_kernel<<<dim3(16, 16), 256>>>(out);
}

// round 9
// speedup vs baseline: 8.0697x; 1.0170x over previous
#include <cuda_runtime.h>
#include <cuda_fp16.h>
#include <math.h>
#include <stdint.h>

#define S_LEN  2048
#define HIDDEN 2048
#define NH     32
#define NKV    8
#define HD     64

// ---------------------------------------------------------------------------
// Device scratch (half data as packed uint32 = half2)
// GEMM "image" layout per row of 1024 words:
//   word (t*16 + 4j + i) holds k-pair p = 16t + j + 4i (halves k=2p,2p+1)
// Q/K transposed images: [head*32 + dimpair][seq] words.
// ---------------------------------------------------------------------------
__device__ uint32_t g_xI   [2048 * 1024];  // x image        [m][k]
__device__ uint32_t g_wqI  [2048 * 1024];  // wq^T image     [n][k]
__device__ uint32_t g_wkI  [ 512 * 1024];  // wk^T image
__device__ uint32_t g_wvI  [ 512 * 1024];  // wv^T image
__device__ uint32_t g_woI  [2048 * 1024];  // wo^T image
__device__ uint32_t g_attnI[2048 * 1024];  // attention out image [s][k]
__device__ uint32_t g_qimg [1024 * 2048];  // q^T image [h*32+dp][s] (pre-scaled)
__device__ uint32_t g_kimg [ 256 * 2048];  // k^T image [kvh*32+dp][s]
__device__ uint32_t g_vh   [2048 * 256];   // v half [s][kvh*32+dp]

// log2(500000)/32
#define L2T_OVER_32 0.5916115177913804f

__device__ __forceinline__ uint32_t h2pack(float lo, float hi) {
    __half2 t = __floats2half2_rn(lo, hi);
    return *(uint32_t*)&t;
}

__device__ __forceinline__ uint32_t smem_u32(const void* p) {
    uint32_t a;
    asm("{ .reg .u64 t; cvta.to.shared.u64 t, %1; cvt.u32.u64 %0, t; }"
        : "=r"(a) : "l"(p));
    return a;
}

__device__ __forceinline__ void mma_fp16(
    float& c0, float& c1, float& c2, float& c3,
    uint32_t a0, uint32_t a1, uint32_t a2, uint32_t a3,
    uint32_t b0, uint32_t b1)
{
    asm volatile(
        "mma.sync.aligned.m16n8k16.row.col.f32.f16.f16.f32 "
        "{%0,%1,%2,%3},{%4,%5,%6,%7},{%8,%9},{%0,%1,%2,%3};"
        : "+f"(c0), "+f"(c1), "+f"(c2), "+f"(c3)
        : "r"(a0), "r"(a1), "r"(a2), "r"(a3), "r"(b0), "r"(b1));
}

#define CP16(dst, src) \
    asm volatile("cp.async.cg.shared.global [%0], [%1], 16;" \
                 :: "r"(dst), "l"(src) : "memory")
#define CP_COMMIT() asm volatile("cp.async.commit_group;" ::: "memory")
#define CP_WAIT(n)  asm volatile("cp.async.wait_group %0;" :: "n"(n) : "memory")

// ---------------------------------------------------------------------------
// Conversion kernels (bandwidth-optimized)
// ---------------------------------------------------------------------------
// x [2048][2048] fp32 -> image [2048][1024 words]; thread = 32-float segment.
__global__ __launch_bounds__(256) void conv_rm_kernel(
    const float* __restrict__ src, uint32_t* __restrict__ dst)
{
    int idx = blockIdx.x * 256 + threadIdx.x;   // 131072 total
    int row = idx >> 6, t = idx & 63;
    const float* s = src + (size_t)row * 2048 + t * 32;
    float f[32];
    #pragma unroll
    for (int w4 = 0; w4 < 8; ++w4)
        *(float4*)&f[4 * w4] = *(const float4*)(s + 4 * w4);
    uint32_t* d = dst + (size_t)row * 1024 + t * 16;
    #pragma unroll
    for (int j = 0; j < 4; ++j) {
        uint4 o;
        o.x = h2pack(f[2 * j +  0], f[2 * j +  1]);
        o.y = h2pack(f[2 * j +  8], f[2 * j +  9]);
        o.z = h2pack(f[2 * j + 16], f[2 * j + 17]);
        o.w = h2pack(f[2 * j + 24], f[2 * j + 25]);
        *(uint4*)&d[4 * j] = o;
    }
}

// All four weights transposed+packed in one launch. blockIdx.z selects.
// Tile: 32 k x 64 n. 256 threads; every thread writes one uint4.
__global__ __launch_bounds__(256) void conv_wT_kernel(
    const float* __restrict__ wq, const float* __restrict__ wk,
    const float* __restrict__ wv, const float* __restrict__ wo,
    uint32_t* __restrict__ wqI, uint32_t* __restrict__ wkI,
    uint32_t* __restrict__ wvI, uint32_t* __restrict__ woI)
{
    const float* w; uint32_t* dst; int N;
    switch (blockIdx.z) {
        case 0:  w = wq; dst = wqI; N = 2048; break;
        case 1:  w = wk; dst = wkI; N = 512;  break;
        case 2:  w = wv; dst = wvI; N = 512;  break;
        default: w = wo; dst = woI; N = 2048; break;
    }
    const int n0 = blockIdx.x * 64;
    if (n0 >= N) return;
    const int k0 = blockIdx.y * 32;
    __shared__ float sm[32][65];
    const int tid = threadIdx.x;
    {
        int lk = tid >> 3, ln = (tid & 7) * 8;
        const float* s = w + (size_t)(k0 + lk) * N + n0 + ln;
        float4 v0 = *(const float4*)(s);
        float4 v1 = *(const float4*)(s + 4);
        sm[lk][ln + 0] = v0.x; sm[lk][ln + 1] = v0.y;
        sm[lk][ln + 2] = v0.z; sm[lk][ln + 3] = v0.w;
        sm[lk][ln + 4] = v1.x; sm[lk][ln + 5] = v1.y;
        sm[lk][ln + 6] = v1.z; sm[lk][ln + 7] = v1.w;
    }
    __syncthreads();
    {
        int n = tid >> 2, j = tid & 3;
        uint4 o;
        o.x = h2pack(sm[2 * j +  0][n], sm[2 * j +  1][n]);
        o.y = h2pack(sm[2 * j +  8][n], sm[2 * j +  9][n]);
        o.z = h2pack(sm[2 * j + 16][n], sm[2 * j + 17][n]);
        o.w = h2pack(sm[2 * j + 24][n], sm[2 * j + 25][n]);
        *(uint4*)&dst[(size_t)(n0 + n) * 1024 + (k0 >> 5) * 16 + 4 * j] = o;
    }
}

// ---------------------------------------------------------------------------
// FP16 GEMM core (unchanged from round 8). Epilogue modes:
//   0: fp32 row-major   1: q image (scale 1/8 + rope)
//   2: k image (rope)   3: v half rows
// ---------------------------------------------------------------------------
#define GNT (HIDDEN / 32)

__device__ __forceinline__ void gemm_half_core(
    const uint32_t* __restrict__ Aimg, const uint32_t* __restrict__ Bimg,
    void* Cout, int N, int bm, int bn, int mode, uint32_t* sAB)
{
    const uint32_t sbase = smem_u32(sAB);
    const int tid  = threadIdx.x;
    const int lane = tid & 31;
    const int wid  = tid >> 5;
    const int g    = lane >> 2;
    const int tg   = lane & 3;
    const int warp_m = (wid >> 1) * 32;
    const int warp_n = (wid & 1) * 64;

    const int prow = tid >> 1;
    const int pj0  = (tid & 1) * 2;
    const int swzP = (prow >> 1) & 3;
    const uint32_t d0 = (uint32_t)(prow * 16 + 4 * (pj0 ^ swzP)) * 4;
    const uint32_t d1 = (uint32_t)(prow * 16 + 4 * ((pj0 + 1) ^ swzP)) * 4;
    const uint32_t* srcA = Aimg + (size_t)(bm + prow) * 1024 + 4 * pj0;
    const uint32_t* srcB = Bimg + (size_t)(bn + prow) * 1024 + 4 * pj0;

    float acc[2][8][4];
    #pragma unroll
    for (int mi = 0; mi < 2; ++mi)
        #pragma unroll
        for (int ni = 0; ni < 8; ++ni)
            #pragma unroll
            for (int c = 0; c < 4; ++c) acc[mi][ni][c] = 0.0f;

#define G_ISSUE(t) do { \
    uint32_t _ab = sbase + ((t) % 3) * 16384; \
    const uint32_t* _sa = srcA + (size_t)(t) * 16; \
    const uint32_t* _sb = srcB + (size_t)(t) * 16; \
    CP16(_ab + d0, _sa); \
    CP16(_ab + d1, _sa + 4); \
    CP16(_ab + 8192 + d0, _sb); \
    CP16(_ab + 8192 + d1, _sb + 4); \
    CP_COMMIT(); \
} while (0)

    G_ISSUE(0);
    G_ISSUE(1);

    for (int t = 0; t < GNT; ++t) {
        if (t < GNT - 1) { CP_WAIT(1); } else { CP_WAIT(0); }
        __syncthreads();
        if (t + 2 < GNT) G_ISSUE(t + 2);

        const uint32_t* As = sAB + (t % 3) * 4096;
        const uint32_t* Bs = As + 2048;

        uint4 va[2], vb[2];
        #pragma unroll
        for (int mi = 0; mi < 2; ++mi) {
            int r0 = warp_m + mi * 16 + g;
            int r1 = r0 + 8;
            va[mi] = *(const uint4*)&As[r0 * 16 + 4 * (tg ^ ((r0 >> 1) & 3))];
            vb[mi] = *(const uint4*)&As[r1 * 16 + 4 * (tg ^ ((r1 >> 1) & 3))];
        }
        #pragma unroll
        for (int ni = 0; ni < 8; ++ni) {
            int rn = warp_n + ni * 8 + g;
            uint4 bv = *(const uint4*)&Bs[rn * 16 + 4 * (tg ^ ((rn >> 1) & 3))];
            #pragma unroll
            for (int mi = 0; mi < 2; ++mi) {
                mma_fp16(acc[mi][ni][0], acc[mi][ni][1],
                         acc[mi][ni][2], acc[mi][ni][3],
                         va[mi].x, vb[mi].x, va[mi].y, vb[mi].y, bv.x, bv.y);
                mma_fp16(acc[mi][ni][0], acc[mi][ni][1],
                         acc[mi][ni][2], acc[mi][ni][3],
                         va[mi].z, vb[mi].z, va[mi].w, vb[mi].w, bv.z, bv.w);
            }
        }
    }
#undef G_ISSUE

    #pragma unroll
    for (int mi = 0; mi < 2; ++mi) {
        #pragma unroll
        for (int ni = 0; ni < 8; ++ni) {
            int row = bm + warp_m + mi * 16 + g;
            int col = bn + warp_n + ni * 8 + tg * 2;
            float c0 = acc[mi][ni][0], c1 = acc[mi][ni][1];
            float c2 = acc[mi][ni][2], c3 = acc[mi][ni][3];
            if (mode == 1) { c0 *= 0.125f; c1 *= 0.125f; c2 *= 0.125f; c3 *= 0.125f; }
            if (mode == 1 || mode == 2) {
                int i = (col & 63) >> 1;
                float freq = exp2f(-(float)i * L2T_OVER_32);
                float sn0, cs0, sn1, cs1;
                sincosf((float)row * freq, &sn0, &cs0);
                sincosf((float)(row + 8) * freq, &sn1, &cs1);
                float r0 = c0 * cs0 - c1 * sn0;
                float r1 = c0 * sn0 + c1 * cs0;
                float r2 = c2 * cs1 - c3 * sn1;
                float r3 = c2 * sn1 + c3 * cs1;
                c0 = r0; c1 = r1; c2 = r2; c3 = r3;
                uint32_t* img = (uint32_t*)Cout;
                int hh = col >> 6;
                int dp = (col & 63) >> 1;
                img[(size_t)(hh * 32 + dp) * 2048 + row]     = h2pack(c0, c1);
                img[(size_t)(hh * 32 + dp) * 2048 + row + 8] = h2pack(c2, c3);
            } else if (mode == 3) {
                uint32_t* vh = (uint32_t*)Cout;
                vh[(size_t)row * 256 + (col >> 1)]       = h2pack(c0, c1);
                vh[(size_t)(row + 8) * 256 + (col >> 1)] = h2pack(c2, c3);
            } else {
                float* Cf = (float*)Cout;
                *(float2*)&Cf[(size_t)row * N + col]       = make_float2(c0, c1);
                *(float2*)&Cf[(size_t)(row + 8) * N + col] = make_float2(c2, c3);
            }
        }
    }
}

__global__ __launch_bounds__(256, 2) void qkv_gemm_kernel(
    uint32_t* __restrict__ qimg, uint32_t* __restrict__ kimg,
    uint32_t* __restrict__ vh)
{
    __shared__ __align__(16) uint32_t sAB[12288];
    const int bx = blockIdx.x;
    const uint32_t* B; void* C; int N, bn, mode;
    if (bx < 16)      { B = g_wqI; C = qimg; N = NH * HD;  bn = bx * 128;        mode = 1; }
    else if (bx < 20) { B = g_wkI; C = kimg; N = NKV * HD; bn = (bx - 16) * 128; mode = 2; }
    else              { B = g_wvI; C = vh;   N = NKV * HD; bn = (bx - 20) * 128; mode = 3; }
    gemm_half_core(g_xI, B, C, N, blockIdx.y * 128, bn, mode, sAB);
}

__global__ __launch_bounds__(256, 2) void out_gemm_kernel(float* __restrict__ out)
{
    __shared__ __align__(16) uint32_t sAB[12288];
    gemm_half_core(g_attnI, g_woI, out, HIDDEN,
                   blockIdx.y * 128, blockIdx.x * 128, 0, sAB);
}

// ---------------------------------------------------------------------------
// Causal GQA flash attention (unchanged from round 8).
// ---------------------------------------------------------------------------
#define AQT   128
#define AKT   64
#define KSTR2 72
#define PSTR2 136
#define KBUF  (32 * KSTR2)
#define ASMEM2 ((4 * KBUF + 32 * PSTR2) * 4)

__global__ __launch_bounds__(256) void attn_mma_kernel(
    const uint32_t* __restrict__ Qimg, const uint32_t* __restrict__ Kimg,
    const uint32_t* __restrict__ Vh, uint32_t* __restrict__ OutI)
{
    extern __shared__ uint32_t dsm[];
    uint32_t* K2 = dsm;
    uint32_t* V2 = dsm + 2 * KBUF;
    uint32_t* P2 = dsm + 4 * KBUF;
    const uint32_t K2b = smem_u32(K2);
    const uint32_t P2b = smem_u32(P2);

    const int h    = blockIdx.y;
    const int kvh  = h >> 2;
    const int qt   = gridDim.x - 1 - blockIdx.x;
    const int q0   = qt * AQT;
    const int tid  = threadIdx.x;
    const int lane = tid & 31;
    const int wid  = tid >> 5;
    const int g    = lane >> 2;
    const int tg   = lane & 3;
    const int warp_m = wid * 16;

    {
        int dp = tid >> 3, seg = (tid & 7) * 16;
        const uint32_t* src = Qimg + (size_t)(h * 32 + dp) * 2048 + q0 + seg;
        uint32_t dst = P2b + (uint32_t)(dp * PSTR2 + seg) * 4;
        CP16(dst, src); CP16(dst + 16, src + 4);
        CP16(dst + 32, src + 8); CP16(dst + 48, src + 12);
    }
    {
        int dp = tid >> 3, seg = (tid & 7) * 8;
        const uint32_t* src = Kimg + (size_t)(kvh * 32 + dp) * 2048 + seg;
        uint32_t dst = K2b + (uint32_t)(dp * KSTR2 + seg) * 4;
        CP16(dst, src); CP16(dst + 16, src + 4);
    }
    CP_COMMIT();
    {
        int kp = tid >> 3, d8 = (tid & 7) * 4;
        const uint32_t* ve = Vh + (size_t)(2 * kp) * 256 + kvh * 32 + d8;
        const uint32_t* vo = Vh + (size_t)(2 * kp + 1) * 256 + kvh * 32 + d8;
        uint4 a = *(const uint4*)ve;
        uint4 b = *(const uint4*)vo;
        uint32_t* dst = &V2[kp * KSTR2 + 2 * d8];
        dst[0] = __byte_perm(a.x, b.x, 0x5410);
        dst[1] = __byte_perm(a.x, b.x, 0x7632);
        dst[2] = __byte_perm(a.y, b.y, 0x5410);
        dst[3] = __byte_perm(a.y, b.y, 0x7632);
        dst[4] = __byte_perm(a.z, b.z, 0x5410);
        dst[5] = __byte_perm(a.z, b.z, 0x7632);
        dst[6] = __byte_perm(a.w, b.w, 0x5410);
        dst[7] = __byte_perm(a.w, b.w, 0x7632);
    }
    CP_WAIT(0);
    __syncthreads();

    uint32_t qf[4][4];
    #pragma unroll
    for (int ks = 0; ks < 4; ++ks) {
        qf[ks][0] = P2[(8 * ks + tg)     * PSTR2 + warp_m + g];
        qf[ks][1] = P2[(8 * ks + tg)     * PSTR2 + warp_m + g + 8];
        qf[ks][2] = P2[(8 * ks + tg + 4) * PSTR2 + warp_m + g];
        qf[ks][3] = P2[(8 * ks + tg + 4) * PSTR2 + warp_m + g + 8];
    }

    float m0 = -INFINITY, m1 = -INFINITY, l0 = 0.0f, l1 = 0.0f;
    float o[8][4];
    #pragma unroll
    for (int ni = 0; ni < 8; ++ni)
        #pragma unroll
        for (int c = 0; c < 4; ++c) o[ni][c] = 0.0f;

    const int ntiles = (q0 + AQT) / AKT;
    for (int t = 0; t < ntiles; ++t) {
        const int cur = t & 1;
        const int nxt = cur ^ 1;
        const int kt  = t * AKT;
        if (t > 0) { CP_WAIT(0); __syncthreads(); }

        const bool havenext = (t + 1 < ntiles);
        uint4 va_, vb_;
        if (havenext) {
            const int ktn = kt + AKT;
            int dp = tid >> 3, seg = (tid & 7) * 8;
            const uint32_t* src = Kimg + (size_t)(kvh * 32 + dp) * 2048 + ktn + seg;
            uint32_t dst = K2b + (uint32_t)(nxt * KBUF + dp * KSTR2 + seg) * 4;
            CP16(dst, src); CP16(dst + 16, src + 4);
            CP_COMMIT();
            int kp = tid >> 3, d8 = (tid & 7) * 4;
            va_ = *(const uint4*)(Vh + (size_t)(ktn + 2 * kp) * 256 + kvh * 32 + d8);
            vb_ = *(const uint4*)(Vh + (size_t)(ktn + 2 * kp + 1) * 256 + kvh * 32 + d8);
        }

        const uint32_t* Kc = K2 + cur * KBUF;
        float sc[8][4];
        #pragma unroll
        for (int ni = 0; ni < 8; ++ni) {
            sc[ni][0] = sc[ni][1] = sc[ni][2] = sc[ni][3] = 0.0f;
            #pragma unroll
            for (int ks = 0; ks < 4; ++ks) {
                uint32_t b0 = Kc[(8 * ks + tg)     * KSTR2 + ni * 8 + g];
                uint32_t b1 = Kc[(8 * ks + tg + 4) * KSTR2 + ni * 8 + g];
                mma_fp16(sc[ni][0], sc[ni][1], sc[ni][2], sc[ni][3],
                         qf[ks][0], qf[ks][1], qf[ks][2], qf[ks][3], b0, b1);
            }
        }

        if (havenext) {
            int kp = tid >> 3, d8 = (tid & 7) * 4;
            uint32_t* dst = &V2[nxt * KBUF + kp * KSTR2 + 2 * d8];
            dst[0] = __byte_perm(va_.x, vb_.x, 0x5410);
            dst[1] = __byte_perm(va_.x, vb_.x, 0x7632);
            dst[2] = __byte_perm(va_.y, vb_.y, 0x5410);
            dst[3] = __byte_perm(va_.y, vb_.y, 0x7632);
            dst[4] = __byte_perm(va_.z, vb_.z, 0x5410);
            dst[5] = __byte_perm(va_.z, vb_.z, 0x7632);
            dst[6] = __byte_perm(va_.w, vb_.w, 0x5410);
            dst[7] = __byte_perm(va_.w, vb_.w, 0x7632);
        }

        const int row0 = q0 + warp_m + g;
        const int row1 = row0 + 8;
        if (kt + AKT - 1 > q0 + warp_m) {
            #pragma unroll
            for (int ni = 0; ni < 8; ++ni) {
                int col = kt + ni * 8 + tg * 2;
                if (col     > row0) sc[ni][0] = -INFINITY;
                if (col + 1 > row0) sc[ni][1] = -INFINITY;
                if (col     > row1) sc[ni][2] = -INFINITY;
                if (col + 1 > row1) sc[ni][3] = -INFINITY;
            }
        }

        float mx0 = -INFINITY, mx1 = -INFINITY;
        #pragma unroll
        for (int ni = 0; ni < 8; ++ni) {
            mx0 = fmaxf(mx0, fmaxf(sc[ni][0], sc[ni][1]));
            mx1 = fmaxf(mx1, fmaxf(sc[ni][2], sc[ni][3]));
        }
        mx0 = fmaxf(mx0, __shfl_xor_sync(0xffffffffu, mx0, 1));
        mx0 = fmaxf(mx0, __shfl_xor_sync(0xffffffffu, mx0, 2));
        mx1 = fmaxf(mx1, __shfl_xor_sync(0xffffffffu, mx1, 1));
        mx1 = fmaxf(mx1, __shfl_xor_sync(0xffffffffu, mx1, 2));

        float mn0 = fmaxf(m0, mx0), mn1 = fmaxf(m1, mx1);
        float cr0 = __expf(m0 - mn0), cr1 = __expf(m1 - mn1);
        m0 = mn0; m1 = mn1;

        float s0 = 0.0f, s1 = 0.0f;
        #pragma unroll
        for (int ni = 0; ni < 8; ++ni) {
            sc[ni][0] = __expf(sc[ni][0] - mn0); s0 += sc[ni][0];
            sc[ni][1] = __expf(sc[ni][1] - mn0); s0 += sc[ni][1];
            sc[ni][2] = __expf(sc[ni][2] - mn1); s1 += sc[ni][2];
            sc[ni][3] = __expf(sc[ni][3] - mn1); s1 += sc[ni][3];
        }
        s0 += __shfl_xor_sync(0xffffffffu, s0, 1);
        s0 += __shfl_xor_sync(0xffffffffu, s0, 2);
        s1 += __shfl_xor_sync(0xffffffffu, s1, 1);
        s1 += __shfl_xor_sync(0xffffffffu, s1, 2);
        l0 = l0 * cr0 + s0;
        l1 = l1 * cr1 + s1;

        #pragma unroll
        for (int ni = 0; ni < 8; ++ni) {
            int kp = ni * 4 + tg;
            P2[kp * PSTR2 + warp_m + g]     = h2pack(sc[ni][0], sc[ni][1]);
            P2[kp * PSTR2 + warp_m + g + 8] = h2pack(sc[ni][2], sc[ni][3]);
        }
        __syncwarp();

        #pragma unroll
        for (int ni = 0; ni < 8; ++ni) {
            o[ni][0] *= cr0; o[ni][1] *= cr0;
            o[ni][2] *= cr1; o[ni][3] *= cr1;
        }

        const uint32_t* Vc = V2 + cur * KBUF;
        #pragma unroll
        for (int ks = 0; ks < 4; ++ks) {
            uint32_t pa0 = P2[(8 * ks + tg)     * PSTR2 + warp_m + g];
            uint32_t pa1 = P2[(8 * ks + tg)     * PSTR2 + warp_m + g + 8];
            uint32_t pa2 = P2[(8 * ks + tg + 4) * PSTR2 + warp_m + g];
            uint32_t pa3 = P2[(8 * ks + tg + 4) * PSTR2 + warp_m + g + 8];
            #pragma unroll
            for (int ni = 0; ni < 8; ++ni) {
                uint32_t b0 = Vc[(8 * ks + tg)     * KSTR2 + ni * 8 + g];
                uint32_t b1 = Vc[(8 * ks + tg + 4) * KSTR2 + ni * 8 + g];
                mma_fp16(o[ni][0], o[ni][1], o[ni][2], o[ni][3],
                         pa0, pa1, pa2, pa3, b0, b1);
            }
        }
    }

    float inv0 = 1.0f / l0, inv1 = 1.0f / l1;
    const int row0 = q0 + warp_m + g;
    #pragma unroll
    for (int ni = 0; ni < 8; ++ni) {
        int p  = h * 32 + ni * 4 + tg;
        int pl = p & 15;
        int w  = (p >> 4) * 16 + 4 * (pl & 3) + (pl >> 2);
        OutI[(size_t)row0 * 1024 + w]       = h2pack(o[ni][0] * inv0, o[ni][1] * inv0);
        OutI[(size_t)(row0 + 8) * 1024 + w] = h2pack(o[ni][2] * inv1, o[ni][3] * inv1);
    }
}

// ---------------------------------------------------------------------------
// Launch
// ---------------------------------------------------------------------------
extern "C" void kernel_launch(void* const* d_in, const int* in_sizes, int n_in,
                              void* d_out, int out_size)
{
    const float* x  = (const float*)d_in[0];
    const float* wq = (const float*)d_in[2];
    const float* wk = (const float*)d_in[3];
    const float* wv = (const float*)d_in[4];
    const float* wo = (const float*)d_in[5];
    float* out = (float*)d_out;

    uint32_t *xI, *wqI, *wkI, *wvI, *woI, *attnI, *qimg, *kimg, *vh;
    cudaGetSymbolAddress((void**)&xI, g_xI);
    cudaGetSymbolAddress((void**)&wqI, g_wqI);
    cudaGetSymbolAddress((void**)&wkI, g_wkI);
    cudaGetSymbolAddress((void**)&wvI, g_wvI);
    cudaGetSymbolAddress((void**)&woI, g_woI);
    cudaGetSymbolAddress((void**)&attnI, g_attnI);
    cudaGetSymbolAddress((void**)&qimg, g_qimg);
    cudaGetSymbolAddress((void**)&kimg, g_kimg);
    cudaGetSymbolAddress((void**)&vh, g_vh);

    cudaFuncSetAttribute(attn_mma_kernel,
                         cudaFuncAttributeMaxDynamicSharedMemorySize, ASMEM2);

    conv_rm_kernel<<<512, 256>>>(x, xI);
    conv_wT_kernel<<<dim3(32, 64, 4), 256>>>(wq, wk, wv, wo, wqI, wkI, wvI, woI);

    qkv_gemm_kernel<<<dim3(24, 16), 256>>>(qimg, kimg, vh);
    attn_mma_kernel<<<dim3(S_LEN / AQT, NH), 256, ASMEM2>>>(qimg, kimg, vh, attnI);
    out_gemm_kernel<<<dim3(16, 16), 256>>>(out);
}